// round 3
// baseline (speedup 1.0000x reference)
#include <cuda_runtime.h>
#include <cstdint>
#include <cstddef>

typedef unsigned long long ull;

// Problem constants
// X:(2,2048,16,64) A:(2,2048,16) B,C:(2,2048,16,64)
// r,k,v,w,bonus:(32,2048,64)  out:(2,2048,1024) f32

// ---------------- device scratch (static globals; no allocation) ------------
__device__ float g_states[2*32*16*64*64];   // per-chunk states (b,c,h,p,n)
__device__ float g_R[2*32*16*64*64];        // prefix state entering chunk c
__device__ float g_eA[1024*64];             // exp(cumA[l]) per (b,c,h)
__device__ float g_expsA[32*32];            // exp(chunk-sum A) per (b,h,c)
__device__ float g_yd[2*2048*1024];         // SSD Y_diag scratch

// ---------------- cp.async + f32x2 helpers -----------------------------------
__device__ __forceinline__ void cp_async16(float* dst, const float* src) {
    unsigned s = (unsigned)__cvta_generic_to_shared(dst);
    asm volatile("cp.async.cg.shared.global [%0], [%1], 16;\n" :: "r"(s), "l"(src));
}
__device__ __forceinline__ void cp_commit() { asm volatile("cp.async.commit_group;\n"); }
__device__ __forceinline__ void cp_wait1()  { asm volatile("cp.async.wait_group 1;\n" ::: "memory"); }
__device__ __forceinline__ void cp_wait0()  { asm volatile("cp.async.wait_group 0;\n" ::: "memory"); }

__device__ __forceinline__ ull f2fma(ull a, ull b, ull c) {
    ull d; asm("fma.rn.f32x2 %0, %1, %2, %3;" : "=l"(d) : "l"(a), "l"(b), "l"(c)); return d;
}
__device__ __forceinline__ ull f2mul(ull a, ull b) {
    ull d; asm("mul.rn.f32x2 %0, %1, %2;" : "=l"(d) : "l"(a), "l"(b)); return d;
}
__device__ __forceinline__ ull f2add(ull a, ull b) {
    ull d; asm("add.rn.f32x2 %0, %1, %2;" : "=l"(d) : "l"(a), "l"(b)); return d;
}
__device__ __forceinline__ ull pk2(float lo, float hi) {
    ull r; asm("mov.b64 %0, {%1, %2};" : "=l"(r) : "f"(lo), "f"(hi)); return r;
}
__device__ __forceinline__ float2 upk2(ull p) {
    float2 f; asm("mov.b64 {%0, %1}, %2;" : "=f"(f.x), "=f"(f.y) : "l"(p)); return f;
}

// ============================================================================
// WKV body: one CTA per batch-head, 256 threads.
// thread t = (i = t>>2, jq = t&3): row i, columns [jq*16, jq*16+16)
// Per step l:  Sk_i = sum_j S[i,j]k_j ; delta_j = v_j - Sk_j
//              S[i,j] = S[i,j]*w_i + (bonus_i*k_i)*delta_j
//              y_i = r_i*(w_i*Sk_i + bonus_i*k_i*(delta . k))
// smem usage: 10240 + 128 floats.
// ============================================================================
__device__ __forceinline__ void wkv_block(
    int bh, int tid, float* sm,
    const float* __restrict__ rr, const float* __restrict__ kk_g,
    const float* __restrict__ vv_g, const float* __restrict__ ww_g,
    const float* __restrict__ bo_g, float* __restrict__ out)
{
    float* s_in = sm;             // [2][5][16][64]
    float* s_sk = sm + 10240;     // [2][64]

    const int b = bh >> 4, h = bh & 15;
    const int i  = tid >> 2;
    const int jq = tid & 3;
    const int jb = jq * 16;
    const size_t base = (size_t)bh * 2048 * 64;
    const float* arrs[5] = { rr, kk_g, vv_g, ww_g, bo_g };
    const int st_ld  = tid >> 4;
    const int off_ld = (tid & 15) * 4;

    ull S2[8];
#pragma unroll
    for (int u = 0; u < 8; ++u) S2[u] = 0ull;

#pragma unroll
    for (int wv = 0; wv < 2; ++wv) {
#pragma unroll
        for (int a = 0; a < 5; ++a)
            cp_async16(&s_in[(wv * 5 + a) * 1024 + st_ld * 64 + off_ld],
                       arrs[a] + base + (size_t)(wv * 16 + st_ld) * 64 + off_ld);
        cp_commit();
    }
    const ull M1 = pk2(-1.f, -1.f);

#pragma unroll 1
    for (int win = 0; win < 128; ++win) {
        const int buf = win & 1;
        if (win >= 126) cp_wait0(); else cp_wait1();
        __syncthreads();
        const float* pr = s_in + buf * 5120;   // [5][16][64]

        // k for step 0 of this window
        ull k2[8];
        {
            const float* k0 = pr + 1024 + jb;
            float4 q0 = *(const float4*)(k0 + 0);
            float4 q1 = *(const float4*)(k0 + 4);
            float4 q2 = *(const float4*)(k0 + 8);
            float4 q3 = *(const float4*)(k0 + 12);
            k2[0] = *(ull*)&q0.x; k2[1] = *(ull*)&q0.z;
            k2[2] = *(ull*)&q1.x; k2[3] = *(ull*)&q1.z;
            k2[4] = *(ull*)&q2.x; k2[5] = *(ull*)&q2.z;
            k2[6] = *(ull*)&q3.x; k2[7] = *(ull*)&q3.z;
        }

#pragma unroll 2
        for (int st = 0; st < 16; ++st) {
            const int par = st & 1;
            // ---- Sk partial dot: 4 parallel packed chains (tree reduce) ----
            ull a0 = f2mul(S2[0], k2[0]);
            ull a1 = f2mul(S2[1], k2[1]);
            ull a2 = f2mul(S2[2], k2[2]);
            ull a3 = f2mul(S2[3], k2[3]);
            a0 = f2fma(S2[4], k2[4], a0);
            a1 = f2fma(S2[5], k2[5], a1);
            a2 = f2fma(S2[6], k2[6], a2);
            a3 = f2fma(S2[7], k2[7], a3);
            a0 = f2add(a0, a1); a2 = f2add(a2, a3); a0 = f2add(a0, a2);
            float2 af = upk2(a0);
            float acc = af.x + af.y;
            acc += __shfl_xor_sync(0xffffffffu, acc, 1);
            acc += __shfl_xor_sync(0xffffffffu, acc, 2);
            if (jq == 0) s_sk[par * 64 + i] = acc;

            // ---- prefetch next step's k before the barrier ----
            ull kn[8];
            if (st < 15) {
                const float* kn0 = pr + 1024 + (st + 1) * 64 + jb;
                float4 q0 = *(const float4*)(kn0 + 0);
                float4 q1 = *(const float4*)(kn0 + 4);
                float4 q2 = *(const float4*)(kn0 + 8);
                float4 q3 = *(const float4*)(kn0 + 12);
                kn[0] = *(ull*)&q0.x; kn[1] = *(ull*)&q0.z;
                kn[2] = *(ull*)&q1.x; kn[3] = *(ull*)&q1.z;
                kn[4] = *(ull*)&q2.x; kn[5] = *(ull*)&q2.z;
                kn[6] = *(ull*)&q3.x; kn[7] = *(ull*)&q3.z;
            }
            __syncthreads();

            const float ri = pr[st * 64 + i];
            const float ki = pr[1024 + st * 64 + i];
            const float wi = pr[3072 + st * 64 + i];
            const float ci = pr[4096 + st * 64 + i] * ki;
            const ull w2 = pk2(wi, wi);
            const ull c2 = pk2(ci, ci);

            // ---- delta + state update ----
            ull d2[8];
#pragma unroll
            for (int q = 0; q < 4; ++q) {
                float4 skq = *(const float4*)(s_sk + par * 64 + jb + 4 * q);
                float4 vq  = *(const float4*)(pr + 2048 + st * 64 + jb + 4 * q);
                ull sk0 = *(ull*)&skq.x, sk1 = *(ull*)&skq.z;
                ull v0  = *(ull*)&vq.x,  v1  = *(ull*)&vq.z;
                d2[2 * q]     = f2fma(sk0, M1, v0);
                d2[2 * q + 1] = f2fma(sk1, M1, v1);
            }
#pragma unroll
            for (int u = 0; u < 8; ++u) S2[u] = f2fma(c2, d2[u], f2mul(S2[u], w2));

            // ---- dk = delta . k (off critical path; feeds y only) ----
            ull b0 = f2mul(d2[0], k2[0]);
            ull b1 = f2mul(d2[1], k2[1]);
            ull b2 = f2mul(d2[2], k2[2]);
            ull b3 = f2mul(d2[3], k2[3]);
            b0 = f2fma(d2[4], k2[4], b0);
            b1 = f2fma(d2[5], k2[5], b1);
            b2 = f2fma(d2[6], k2[6], b2);
            b3 = f2fma(d2[7], k2[7], b3);
            b0 = f2add(b0, b1); b2 = f2add(b2, b3); b0 = f2add(b0, b2);
            float2 bf = upk2(b0);
            float dk = bf.x + bf.y;
            dk += __shfl_xor_sync(0xffffffffu, dk, 1);
            dk += __shfl_xor_sync(0xffffffffu, dk, 2);
            if (jq == 0) {
                const int l = win * 16 + st;
                out[(size_t)(b * 2048 + l) * 1024 + h * 64 + i] =
                    ri * fmaf(ci, dk, wi * acc);    // pure write
            }
            if (st < 15) {
#pragma unroll
                for (int u = 0; u < 8; ++u) k2[u] = kn[u];
            }
        }

        if (win + 2 < 128) {
#pragma unroll
            for (int a = 0; a < 5; ++a)
                cp_async16(&s_in[(buf * 5 + a) * 1024 + st_ld * 64 + off_ld],
                           arrs[a] + base + (size_t)((win + 2) * 16 + st_ld) * 64 + off_ld);
            cp_commit();
        }
    }
}

// ============================================================================
// SSD per-chunk body (writes Y_diag to g_yd; states to g_states)
// smem: sB[64][65], sG[64][65], sX[64][64], cum/eA/ieA[64] = 50432 bytes
// ============================================================================
__device__ __forceinline__ void ssd_chunk_body(
    int blk, int tid, float* sm,
    const float* __restrict__ X, const float* __restrict__ A,
    const float* __restrict__ Bm, const float* __restrict__ Cm)
{
    float* sB   = sm;
    float* sG   = sm + 64 * 65;
    float* sX   = sm + 2 * 64 * 65;
    float* s_cum = sX + 4096;
    float* s_eA  = s_cum + 64;
    float* s_ieA = s_eA + 64;

    const int h  = blk & 15;
    const int cc = (blk >> 4) & 31;
    const int b  = blk >> 9;

    const size_t gbase = ((size_t)(b * 2048 + cc * 64) * 16 + h) * 64;
#pragma unroll
    for (int u = 0; u < 4; ++u) {
        int idx4 = u * 256 + tid;
        int l = idx4 >> 4, n4 = (idx4 & 15) * 4;
        size_t go = gbase + (size_t)l * 1024 + n4;
        float4 bv = *(const float4*)(Bm + go);
        float4 cv = *(const float4*)(Cm + go);
        float4 xv = *(const float4*)(X + go);
        float* pb = sB + l * 65 + n4;
        pb[0] = bv.x; pb[1] = bv.y; pb[2] = bv.z; pb[3] = bv.w;
        float* pc = sG + l * 65 + n4;
        pc[0] = cv.x; pc[1] = cv.y; pc[2] = cv.z; pc[3] = cv.w;
        *(float4*)(sX + l * 64 + n4) = xv;
    }
    if (tid < 64) {
        float x = A[(size_t)(b * 2048 + cc * 64 + tid) * 16 + h];
#pragma unroll
        for (int o = 1; o < 32; o <<= 1) {
            float t = __shfl_up_sync(0xffffffffu, x, o);
            if ((tid & 31) >= o) x += t;
        }
        s_cum[tid] = x;
    }
    __syncthreads();
    if (tid < 64) {
        float x = s_cum[tid] + ((tid >= 32) ? s_cum[31] : 0.f);
        float e = expf(x);
        s_eA[tid]  = e;
        s_ieA[tid] = expf(-x);
        g_eA[(size_t)blk * 64 + tid] = e;
        if (tid == 63) g_expsA[(b * 16 + h) * 32 + cc] = e;
    }
    __syncthreads();

    const int tl = tid >> 4, ts = tid & 15;
    const int r0 = tl * 4, c0 = ts * 4;

    // G = dot(C_l, B_s)
    float g[4][4];
#pragma unroll
    for (int ii = 0; ii < 4; ++ii)
#pragma unroll
        for (int jj = 0; jj < 4; ++jj) g[ii][jj] = 0.f;
    for (int n = 0; n < 64; ++n) {
        float cl[4], bsv[4];
#pragma unroll
        for (int ii = 0; ii < 4; ++ii) cl[ii] = sG[(r0 + ii) * 65 + n];
#pragma unroll
        for (int jj = 0; jj < 4; ++jj) bsv[jj] = sB[(c0 + jj) * 65 + n];
#pragma unroll
        for (int ii = 0; ii < 4; ++ii)
#pragma unroll
            for (int jj = 0; jj < 4; ++jj) g[ii][jj] = fmaf(cl[ii], bsv[jj], g[ii][jj]);
    }
    __syncthreads();
#pragma unroll
    for (int ii = 0; ii < 4; ++ii) {
        int l = r0 + ii;
        float el = s_eA[l];
#pragma unroll
        for (int jj = 0; jj < 4; ++jj) {
            int s = c0 + jj;
            sG[l * 65 + s] = (s <= l) ? g[ii][jj] * el * s_ieA[s] : 0.f;
        }
    }
    __syncthreads();

    // Y_diag
    float y[4][4];
#pragma unroll
    for (int ii = 0; ii < 4; ++ii)
#pragma unroll
        for (int jj = 0; jj < 4; ++jj) y[ii][jj] = 0.f;
    for (int s = 0; s < 64; ++s) {
        float4 xv = *(const float4*)(sX + s * 64 + c0);
        float gl[4];
#pragma unroll
        for (int ii = 0; ii < 4; ++ii) gl[ii] = sG[(r0 + ii) * 65 + s];
#pragma unroll
        for (int ii = 0; ii < 4; ++ii) {
            y[ii][0] = fmaf(gl[ii], xv.x, y[ii][0]);
            y[ii][1] = fmaf(gl[ii], xv.y, y[ii][1]);
            y[ii][2] = fmaf(gl[ii], xv.z, y[ii][2]);
            y[ii][3] = fmaf(gl[ii], xv.w, y[ii][3]);
        }
    }
#pragma unroll
    for (int ii = 0; ii < 4; ++ii) {
        int l = r0 + ii;
        *(float4*)(g_yd + (size_t)(b * 2048 + cc * 64 + l) * 1024 + h * 64 + c0) =
            make_float4(y[ii][0], y[ii][1], y[ii][2], y[ii][3]);
    }

    // chunk states
    float stt[4][4];
#pragma unroll
    for (int ii = 0; ii < 4; ++ii)
#pragma unroll
        for (int jj = 0; jj < 4; ++jj) stt[ii][jj] = 0.f;
    const float eA63 = s_eA[63];
    for (int l = 0; l < 64; ++l) {
        float ds = eA63 * s_ieA[l];
        float4 xv = *(const float4*)(sX + l * 64 + r0);
        float xw[4] = { xv.x * ds, xv.y * ds, xv.z * ds, xv.w * ds };
        float bv[4];
#pragma unroll
        for (int jj = 0; jj < 4; ++jj) bv[jj] = sB[l * 65 + c0 + jj];
#pragma unroll
        for (int ii = 0; ii < 4; ++ii)
#pragma unroll
            for (int jj = 0; jj < 4; ++jj) stt[ii][jj] = fmaf(xw[ii], bv[jj], stt[ii][jj]);
    }
#pragma unroll
    for (int ii = 0; ii < 4; ++ii)
        *(float4*)(g_states + (size_t)blk * 4096 + (size_t)(r0 + ii) * 64 + c0) =
            make_float4(stt[ii][0], stt[ii][1], stt[ii][2], stt[ii][3]);
}

// ============================================================================
// Fused: blockIdx 0..31 -> WKV (long), 32..1055 -> SSD chunk (overlapped)
// ============================================================================
__global__ void __launch_bounds__(256, 2) fused_kernel(
    const float* __restrict__ X, const float* __restrict__ A,
    const float* __restrict__ Bm, const float* __restrict__ Cm,
    const float* __restrict__ rr, const float* __restrict__ kk,
    const float* __restrict__ vv, const float* __restrict__ ww,
    const float* __restrict__ bo, float* __restrict__ out)
{
    extern __shared__ float sm[];
    if (blockIdx.x < 32) {
        wkv_block(blockIdx.x, threadIdx.x, sm, rr, kk, vv, ww, bo, out);
    } else {
        ssd_chunk_body(blockIdx.x - 32, threadIdx.x, sm, X, A, Bm, Cm);
    }
}

// ============================================================================
// K2: inter-chunk decay scan
// ============================================================================
__global__ void __launch_bounds__(1024) scan_kernel()
{
    const int bid = blockIdx.x;
    const int bh = bid >> 2, q = bid & 3;
    const int b = bh >> 4, h = bh & 15;
    const int e = q * 1024 + threadIdx.x;
    float R = 0.f;
    const float* es = g_expsA + bh * 32;
#pragma unroll 1
    for (int c = 0; c < 32; ++c) {
        size_t idx = (size_t)(b * 512 + c * 16 + h) * 4096 + e;
        g_R[idx] = R;
        R = fmaf(R, es[c], g_states[idx]);
    }
}

// ============================================================================
// K3: out += g_yd + eA[l] * (C . R^T)
// ============================================================================
__global__ void __launch_bounds__(256) ssd_off_kernel(
    const float* __restrict__ Cm, float* __restrict__ out)
{
    __shared__ float sC[64 * 65];
    __shared__ float sR[64 * 65];
    __shared__ float s_e[64];
    const int blk = blockIdx.x;
    const int h  = blk & 15;
    const int cc = (blk >> 4) & 31;
    const int b  = blk >> 9;
    const int tid = threadIdx.x;

    const size_t gbase = ((size_t)(b * 2048 + cc * 64) * 16 + h) * 64;
#pragma unroll
    for (int u = 0; u < 4; ++u) {
        int idx4 = u * 256 + tid;
        int l = idx4 >> 4, n4 = (idx4 & 15) * 4;
        float4 cv = *(const float4*)(Cm + gbase + (size_t)l * 1024 + n4);
        float4 rv = *(const float4*)(g_R + (size_t)blk * 4096 + (size_t)idx4 * 4);
        float* pc = sC + l * 65 + n4;
        pc[0] = cv.x; pc[1] = cv.y; pc[2] = cv.z; pc[3] = cv.w;
        float* pr = sR + l * 65 + n4;
        pr[0] = rv.x; pr[1] = rv.y; pr[2] = rv.z; pr[3] = rv.w;
    }
    if (tid < 64) s_e[tid] = g_eA[(size_t)blk * 64 + tid];
    __syncthreads();

    const int tl = tid >> 4, ts = tid & 15;
    const int l0 = tl * 4, p0 = ts * 4;

    float acc[4][4];
#pragma unroll
    for (int ii = 0; ii < 4; ++ii)
#pragma unroll
        for (int jj = 0; jj < 4; ++jj) acc[ii][jj] = 0.f;

    for (int n = 0; n < 64; ++n) {
        float cl[4], rv[4];
#pragma unroll
        for (int ii = 0; ii < 4; ++ii) cl[ii] = sC[(l0 + ii) * 65 + n];
#pragma unroll
        for (int jj = 0; jj < 4; ++jj) rv[jj] = sR[(p0 + jj) * 65 + n];
#pragma unroll
        for (int ii = 0; ii < 4; ++ii)
#pragma unroll
            for (int jj = 0; jj < 4; ++jj) acc[ii][jj] = fmaf(cl[ii], rv[jj], acc[ii][jj]);
    }
#pragma unroll
    for (int ii = 0; ii < 4; ++ii) {
        int l = l0 + ii;
        float e = s_e[l];
        size_t ofs = (size_t)(b * 2048 + cc * 64 + l) * 1024 + h * 64 + p0;
        float4* po = (float4*)(out + ofs);
        float4 o  = *po;
        float4 yd = *(const float4*)(g_yd + ofs);
        o.x += yd.x + e * acc[ii][0];
        o.y += yd.y + e * acc[ii][1];
        o.z += yd.z + e * acc[ii][2];
        o.w += yd.w + e * acc[ii][3];
        *po = o;
    }
}

// ============================================================================
extern "C" void kernel_launch(void* const* d_in, const int* in_sizes, int n_in,
                              void* d_out, int out_size)
{
    (void)in_sizes; (void)n_in; (void)out_size;
    const float* X  = (const float*)d_in[0];
    const float* A  = (const float*)d_in[1];
    const float* B  = (const float*)d_in[2];
    const float* C  = (const float*)d_in[3];
    const float* r  = (const float*)d_in[4];
    const float* k  = (const float*)d_in[5];
    const float* v  = (const float*)d_in[6];
    const float* w  = (const float*)d_in[7];
    const float* bo = (const float*)d_in[8];
    float* out = (float*)d_out;

    const int FUSED_SMEM = (2 * 64 * 65 + 64 * 64 + 3 * 64) * 4;  // 50432 B
    cudaFuncSetAttribute(fused_kernel,
                         cudaFuncAttributeMaxDynamicSharedMemorySize, FUSED_SMEM);

    fused_kernel<<<1056, 256, FUSED_SMEM>>>(X, A, B, C, r, k, v, w, bo, out);
    scan_kernel<<<128, 1024>>>();
    ssd_off_kernel<<<1024, 256>>>(C, out);
}

// round 4
// speedup vs baseline: 1.2141x; 1.2141x over previous
#include <cuda_runtime.h>
#include <cstdint>
#include <cstddef>

typedef unsigned long long ull;

// Problem constants
// X:(2,2048,16,64) A:(2,2048,16) B,C:(2,2048,16,64)
// r,k,v,w,bonus:(32,2048,64)  out:(2,2048,1024) f32

// ---------------- device scratch (static globals; no allocation) ------------
__device__ float g_states[2*32*16*64*64];   // per-chunk states (b,c,h,p,n)
__device__ float g_R[2*32*16*64*64];        // prefix state entering chunk c
__device__ float g_eA[1024*64];             // exp(cumA[l]) per (b,c,h)
__device__ float g_expsA[32*32];            // exp(chunk-sum A) per (b,h,c)
__device__ float g_yd[2*2048*1024];         // SSD Y_diag scratch

// ---------------- cp.async + f32x2 helpers -----------------------------------
__device__ __forceinline__ void cp_async16(float* dst, const float* src) {
    unsigned s = (unsigned)__cvta_generic_to_shared(dst);
    asm volatile("cp.async.cg.shared.global [%0], [%1], 16;\n" :: "r"(s), "l"(src));
}
__device__ __forceinline__ void cp_commit() { asm volatile("cp.async.commit_group;\n"); }
__device__ __forceinline__ void cp_wait1()  { asm volatile("cp.async.wait_group 1;\n" ::: "memory"); }
__device__ __forceinline__ void cp_wait0()  { asm volatile("cp.async.wait_group 0;\n" ::: "memory"); }

__device__ __forceinline__ ull f2fma(ull a, ull b, ull c) {
    ull d; asm("fma.rn.f32x2 %0, %1, %2, %3;" : "=l"(d) : "l"(a), "l"(b), "l"(c)); return d;
}
__device__ __forceinline__ ull f2mul(ull a, ull b) {
    ull d; asm("mul.rn.f32x2 %0, %1, %2;" : "=l"(d) : "l"(a), "l"(b)); return d;
}
__device__ __forceinline__ ull f2add(ull a, ull b) {
    ull d; asm("add.rn.f32x2 %0, %1, %2;" : "=l"(d) : "l"(a), "l"(b)); return d;
}
__device__ __forceinline__ ull pk2(float lo, float hi) {
    ull r; asm("mov.b64 %0, {%1, %2};" : "=l"(r) : "f"(lo), "f"(hi)); return r;
}
__device__ __forceinline__ float2 upk2(ull p) {
    float2 f; asm("mov.b64 {%0, %1}, %2;" : "=f"(f.x), "=f"(f.y) : "l"(p)); return f;
}

// ============================================================================
// WKV body: one CTA per batch-head, 256 threads.
// thread t = (i = t>>2, jq = t&3): row i, columns [jq*16, jq*16+16)
// Sequential loop per step: ONLY the recurrence
//   Sk_i = sum_j S[i,j] k_j          (dot + 2 shfl + smem exchange)
//   delta_j = v_j - Sk_j
//   S[i,j] = S[i,j]*w_i + (bonus_i*k_i)*delta_j
// Output y batched per 16-step window:
//   dk[st] = sum_j (v_j - Sk_j) k_j   (one warp-dot per step)
//   y_i    = r_i*(w_i*Sk_i + bonus_i*k_i*dk)
// smem: s_in[2][5][16][64] + s_sk[16][64] + s_dk[16]  (45 KB)
// ============================================================================
__device__ __forceinline__ void wkv_block(
    int bh, int tid, float* sm,
    const float* __restrict__ rr, const float* __restrict__ kk_g,
    const float* __restrict__ vv_g, const float* __restrict__ ww_g,
    const float* __restrict__ bo_g, float* __restrict__ out)
{
    float* s_in = sm;             // [2][5][16][64] = 10240 floats
    float* s_sk = sm + 10240;     // [16][64]
    float* s_dk = sm + 11264;     // [16]

    const int b = bh >> 4, h = bh & 15;
    const int i  = tid >> 2;
    const int jq = tid & 3;
    const int jb = jq * 16;
    const size_t base = (size_t)bh * 2048 * 64;
    const float* arrs[5] = { rr, kk_g, vv_g, ww_g, bo_g };
    const int st_ld  = tid >> 4;
    const int off_ld = (tid & 15) * 4;
    const int lane = tid & 31, wid = tid >> 5;

    ull S2[8];
#pragma unroll
    for (int u = 0; u < 8; ++u) S2[u] = 0ull;

#pragma unroll
    for (int wv = 0; wv < 2; ++wv) {
#pragma unroll
        for (int a = 0; a < 5; ++a)
            cp_async16(&s_in[(wv * 5 + a) * 1024 + st_ld * 64 + off_ld],
                       arrs[a] + base + (size_t)(wv * 16 + st_ld) * 64 + off_ld);
        cp_commit();
    }
    const ull M1 = pk2(-1.f, -1.f);

#pragma unroll 1
    for (int win = 0; win < 128; ++win) {
        const int buf = win & 1;
        if (win >= 126) cp_wait0(); else cp_wait1();
        __syncthreads();
        const float* pr = s_in + buf * 5120;   // [5][16][64]

        // ---------------- sequential recurrence (lean) ----------------
#pragma unroll 1
        for (int st = 0; st < 16; ++st) {
            const float* kk_s = pr + 1024 + st * 64;

            // k for my 16 columns
            ull k2[8];
            {
                float4 q0 = *(const float4*)(kk_s + jb + 0);
                float4 q1 = *(const float4*)(kk_s + jb + 4);
                float4 q2 = *(const float4*)(kk_s + jb + 8);
                float4 q3 = *(const float4*)(kk_s + jb + 12);
                k2[0] = *(ull*)&q0.x; k2[1] = *(ull*)&q0.z;
                k2[2] = *(ull*)&q1.x; k2[3] = *(ull*)&q1.z;
                k2[4] = *(ull*)&q2.x; k2[5] = *(ull*)&q2.z;
                k2[6] = *(ull*)&q3.x; k2[7] = *(ull*)&q3.z;
            }

            // Sk partial dot (4 independent packed chains, tree reduce)
            ull a0 = f2mul(S2[0], k2[0]);
            ull a1 = f2mul(S2[1], k2[1]);
            ull a2 = f2mul(S2[2], k2[2]);
            ull a3 = f2mul(S2[3], k2[3]);
            a0 = f2fma(S2[4], k2[4], a0);
            a1 = f2fma(S2[5], k2[5], a1);
            a2 = f2fma(S2[6], k2[6], a2);
            a3 = f2fma(S2[7], k2[7], a3);
            a0 = f2add(a0, a1); a2 = f2add(a2, a3); a0 = f2add(a0, a2);
            float2 af = upk2(a0);
            float acc = af.x + af.y;
            acc += __shfl_xor_sync(0xffffffffu, acc, 1);
            acc += __shfl_xor_sync(0xffffffffu, acc, 2);
            if (jq == 0) s_sk[st * 64 + i] = acc;
            __syncthreads();

            const float wi = pr[3072 + st * 64 + i];
            const float ki = kk_s[i];
            const float ci = pr[4096 + st * 64 + i] * ki;
            const ull w2 = pk2(wi, wi);
            const ull c2 = pk2(ci, ci);

            // delta + state update
            ull d2[8];
#pragma unroll
            for (int q = 0; q < 4; ++q) {
                float4 skq = *(const float4*)(s_sk + st * 64 + jb + 4 * q);
                float4 vq  = *(const float4*)(pr + 2048 + st * 64 + jb + 4 * q);
                ull sk0 = *(ull*)&skq.x, sk1 = *(ull*)&skq.z;
                ull v0  = *(ull*)&vq.x,  v1  = *(ull*)&vq.z;
                d2[2 * q]     = f2fma(sk0, M1, v0);
                d2[2 * q + 1] = f2fma(sk1, M1, v1);
            }
#pragma unroll
            for (int u = 0; u < 8; ++u) S2[u] = f2fma(c2, d2[u], f2mul(S2[u], w2));
        }

        // ---------------- dk[st] = (v - Sk) . k : warp-dots ----------------
        // s_sk complete (each step's store precedes that step's barrier).
#pragma unroll
        for (int rep = 0; rep < 2; ++rep) {
            const int st = wid + rep * 8;
            const float* kk_s = pr + 1024 + st * 64;
            const float* vv_s = pr + 2048 + st * 64;
            const float* sk_s = s_sk + st * 64;
            float2 kv = *(const float2*)(kk_s + lane * 2);
            float2 vv2 = *(const float2*)(vv_s + lane * 2);
            float2 sk2 = *(const float2*)(sk_s + lane * 2);
            float pd = fmaf(vv2.x - sk2.x, kv.x, (vv2.y - sk2.y) * kv.y);
#pragma unroll
            for (int off = 16; off > 0; off >>= 1)
                pd += __shfl_xor_sync(0xffffffffu, pd, off);
            if (lane == 0) s_dk[st] = pd;
        }
        __syncthreads();

        // ---------------- batched y: coalesced stores ----------------
#pragma unroll
        for (int u = 0; u < 4; ++u) {
            const int idx = u * 256 + tid;      // 0..1023
            const int st = idx >> 6, ii = idx & 63;
            const float Sk = s_sk[st * 64 + ii];
            const float r_ = pr[st * 64 + ii];
            const float k_ = pr[1024 + st * 64 + ii];
            const float w_ = pr[3072 + st * 64 + ii];
            const float b_ = pr[4096 + st * 64 + ii];
            const float dk = s_dk[st];
            const float y = r_ * fmaf(b_ * k_, dk, w_ * Sk);
            out[(size_t)(b * 2048 + win * 16 + st) * 1024 + h * 64 + ii] = y;
        }
        __syncthreads();   // all reads of buf done before refill

        if (win + 2 < 128) {
#pragma unroll
            for (int a = 0; a < 5; ++a)
                cp_async16(&s_in[(buf * 5 + a) * 1024 + st_ld * 64 + off_ld],
                           arrs[a] + base + (size_t)((win + 2) * 16 + st_ld) * 64 + off_ld);
            cp_commit();
        }
    }
}

// ============================================================================
// SSD per-chunk body (writes Y_diag to g_yd; states to g_states)
// smem: sB[64][65], sG[64][65], sX[64][64], cum/eA/ieA[64] = 50432 bytes
// ============================================================================
__device__ __forceinline__ void ssd_chunk_body(
    int blk, int tid, float* sm,
    const float* __restrict__ X, const float* __restrict__ A,
    const float* __restrict__ Bm, const float* __restrict__ Cm)
{
    float* sB   = sm;
    float* sG   = sm + 64 * 65;
    float* sX   = sm + 2 * 64 * 65;
    float* s_cum = sX + 4096;
    float* s_eA  = s_cum + 64;
    float* s_ieA = s_eA + 64;

    const int h  = blk & 15;
    const int cc = (blk >> 4) & 31;
    const int b  = blk >> 9;

    const size_t gbase = ((size_t)(b * 2048 + cc * 64) * 16 + h) * 64;
#pragma unroll
    for (int u = 0; u < 4; ++u) {
        int idx4 = u * 256 + tid;
        int l = idx4 >> 4, n4 = (idx4 & 15) * 4;
        size_t go = gbase + (size_t)l * 1024 + n4;
        float4 bv = *(const float4*)(Bm + go);
        float4 cv = *(const float4*)(Cm + go);
        float4 xv = *(const float4*)(X + go);
        float* pb = sB + l * 65 + n4;
        pb[0] = bv.x; pb[1] = bv.y; pb[2] = bv.z; pb[3] = bv.w;
        float* pc = sG + l * 65 + n4;
        pc[0] = cv.x; pc[1] = cv.y; pc[2] = cv.z; pc[3] = cv.w;
        *(float4*)(sX + l * 64 + n4) = xv;
    }
    if (tid < 64) {
        float x = A[(size_t)(b * 2048 + cc * 64 + tid) * 16 + h];
#pragma unroll
        for (int o = 1; o < 32; o <<= 1) {
            float t = __shfl_up_sync(0xffffffffu, x, o);
            if ((tid & 31) >= o) x += t;
        }
        s_cum[tid] = x;
    }
    __syncthreads();
    if (tid < 64) {
        float x = s_cum[tid] + ((tid >= 32) ? s_cum[31] : 0.f);
        float e = expf(x);
        s_eA[tid]  = e;
        s_ieA[tid] = expf(-x);
        g_eA[(size_t)blk * 64 + tid] = e;
        if (tid == 63) g_expsA[(b * 16 + h) * 32 + cc] = e;
    }
    __syncthreads();

    const int tl = tid >> 4, ts = tid & 15;
    const int r0 = tl * 4, c0 = ts * 4;

    // G = dot(C_l, B_s)
    float g[4][4];
#pragma unroll
    for (int ii = 0; ii < 4; ++ii)
#pragma unroll
        for (int jj = 0; jj < 4; ++jj) g[ii][jj] = 0.f;
    for (int n = 0; n < 64; ++n) {
        float cl[4], bsv[4];
#pragma unroll
        for (int ii = 0; ii < 4; ++ii) cl[ii] = sG[(r0 + ii) * 65 + n];
#pragma unroll
        for (int jj = 0; jj < 4; ++jj) bsv[jj] = sB[(c0 + jj) * 65 + n];
#pragma unroll
        for (int ii = 0; ii < 4; ++ii)
#pragma unroll
            for (int jj = 0; jj < 4; ++jj) g[ii][jj] = fmaf(cl[ii], bsv[jj], g[ii][jj]);
    }
    __syncthreads();
#pragma unroll
    for (int ii = 0; ii < 4; ++ii) {
        int l = r0 + ii;
        float el = s_eA[l];
#pragma unroll
        for (int jj = 0; jj < 4; ++jj) {
            int s = c0 + jj;
            sG[l * 65 + s] = (s <= l) ? g[ii][jj] * el * s_ieA[s] : 0.f;
        }
    }
    __syncthreads();

    // Y_diag
    float y[4][4];
#pragma unroll
    for (int ii = 0; ii < 4; ++ii)
#pragma unroll
        for (int jj = 0; jj < 4; ++jj) y[ii][jj] = 0.f;
    for (int s = 0; s < 64; ++s) {
        float4 xv = *(const float4*)(sX + s * 64 + c0);
        float gl[4];
#pragma unroll
        for (int ii = 0; ii < 4; ++ii) gl[ii] = sG[(r0 + ii) * 65 + s];
#pragma unroll
        for (int ii = 0; ii < 4; ++ii) {
            y[ii][0] = fmaf(gl[ii], xv.x, y[ii][0]);
            y[ii][1] = fmaf(gl[ii], xv.y, y[ii][1]);
            y[ii][2] = fmaf(gl[ii], xv.z, y[ii][2]);
            y[ii][3] = fmaf(gl[ii], xv.w, y[ii][3]);
        }
    }
#pragma unroll
    for (int ii = 0; ii < 4; ++ii) {
        int l = r0 + ii;
        *(float4*)(g_yd + (size_t)(b * 2048 + cc * 64 + l) * 1024 + h * 64 + c0) =
            make_float4(y[ii][0], y[ii][1], y[ii][2], y[ii][3]);
    }

    // chunk states
    float stt[4][4];
#pragma unroll
    for (int ii = 0; ii < 4; ++ii)
#pragma unroll
        for (int jj = 0; jj < 4; ++jj) stt[ii][jj] = 0.f;
    const float eA63 = s_eA[63];
    for (int l = 0; l < 64; ++l) {
        float ds = eA63 * s_ieA[l];
        float4 xv = *(const float4*)(sX + l * 64 + r0);
        float xw[4] = { xv.x * ds, xv.y * ds, xv.z * ds, xv.w * ds };
        float bv[4];
#pragma unroll
        for (int jj = 0; jj < 4; ++jj) bv[jj] = sB[l * 65 + c0 + jj];
#pragma unroll
        for (int ii = 0; ii < 4; ++ii)
#pragma unroll
            for (int jj = 0; jj < 4; ++jj) stt[ii][jj] = fmaf(xw[ii], bv[jj], stt[ii][jj]);
    }
#pragma unroll
    for (int ii = 0; ii < 4; ++ii)
        *(float4*)(g_states + (size_t)blk * 4096 + (size_t)(r0 + ii) * 64 + c0) =
            make_float4(stt[ii][0], stt[ii][1], stt[ii][2], stt[ii][3]);
}

// ============================================================================
// Fused: blockIdx 0..31 -> WKV (long), 32..1055 -> SSD chunk (overlapped)
// ============================================================================
__global__ void __launch_bounds__(256, 2) fused_kernel(
    const float* __restrict__ X, const float* __restrict__ A,
    const float* __restrict__ Bm, const float* __restrict__ Cm,
    const float* __restrict__ rr, const float* __restrict__ kk,
    const float* __restrict__ vv, const float* __restrict__ ww,
    const float* __restrict__ bo, float* __restrict__ out)
{
    extern __shared__ float sm[];
    if (blockIdx.x < 32) {
        wkv_block(blockIdx.x, threadIdx.x, sm, rr, kk, vv, ww, bo, out);
    } else {
        ssd_chunk_body(blockIdx.x - 32, threadIdx.x, sm, X, A, Bm, Cm);
    }
}

// ============================================================================
// K2: inter-chunk decay scan
// ============================================================================
__global__ void __launch_bounds__(1024) scan_kernel()
{
    const int bid = blockIdx.x;
    const int bh = bid >> 2, q = bid & 3;
    const int b = bh >> 4, h = bh & 15;
    const int e = q * 1024 + threadIdx.x;
    float R = 0.f;
    const float* es = g_expsA + bh * 32;
#pragma unroll 1
    for (int c = 0; c < 32; ++c) {
        size_t idx = (size_t)(b * 512 + c * 16 + h) * 4096 + e;
        g_R[idx] = R;
        R = fmaf(R, es[c], g_states[idx]);
    }
}

// ============================================================================
// K3: out += g_yd + eA[l] * (C . R^T)
// ============================================================================
__global__ void __launch_bounds__(256) ssd_off_kernel(
    const float* __restrict__ Cm, float* __restrict__ out)
{
    __shared__ float sC[64 * 65];
    __shared__ float sR[64 * 65];
    __shared__ float s_e[64];
    const int blk = blockIdx.x;
    const int h  = blk & 15;
    const int cc = (blk >> 4) & 31;
    const int b  = blk >> 9;
    const int tid = threadIdx.x;

    const size_t gbase = ((size_t)(b * 2048 + cc * 64) * 16 + h) * 64;
#pragma unroll
    for (int u = 0; u < 4; ++u) {
        int idx4 = u * 256 + tid;
        int l = idx4 >> 4, n4 = (idx4 & 15) * 4;
        float4 cv = *(const float4*)(Cm + gbase + (size_t)l * 1024 + n4);
        float4 rv = *(const float4*)(g_R + (size_t)blk * 4096 + (size_t)idx4 * 4);
        float* pc = sC + l * 65 + n4;
        pc[0] = cv.x; pc[1] = cv.y; pc[2] = cv.z; pc[3] = cv.w;
        float* pr = sR + l * 65 + n4;
        pr[0] = rv.x; pr[1] = rv.y; pr[2] = rv.z; pr[3] = rv.w;
    }
    if (tid < 64) s_e[tid] = g_eA[(size_t)blk * 64 + tid];
    __syncthreads();

    const int tl = tid >> 4, ts = tid & 15;
    const int l0 = tl * 4, p0 = ts * 4;

    float acc[4][4];
#pragma unroll
    for (int ii = 0; ii < 4; ++ii)
#pragma unroll
        for (int jj = 0; jj < 4; ++jj) acc[ii][jj] = 0.f;

    for (int n = 0; n < 64; ++n) {
        float cl[4], rv[4];
#pragma unroll
        for (int ii = 0; ii < 4; ++ii) cl[ii] = sC[(l0 + ii) * 65 + n];
#pragma unroll
        for (int jj = 0; jj < 4; ++jj) rv[jj] = sR[(p0 + jj) * 65 + n];
#pragma unroll
        for (int ii = 0; ii < 4; ++ii)
#pragma unroll
            for (int jj = 0; jj < 4; ++jj) acc[ii][jj] = fmaf(cl[ii], rv[jj], acc[ii][jj]);
    }
#pragma unroll
    for (int ii = 0; ii < 4; ++ii) {
        int l = l0 + ii;
        float e = s_e[l];
        size_t ofs = (size_t)(b * 2048 + cc * 64 + l) * 1024 + h * 64 + p0;
        float4* po = (float4*)(out + ofs);
        float4 o  = *po;
        float4 yd = *(const float4*)(g_yd + ofs);
        o.x += yd.x + e * acc[ii][0];
        o.y += yd.y + e * acc[ii][1];
        o.z += yd.z + e * acc[ii][2];
        o.w += yd.w + e * acc[ii][3];
        *po = o;
    }
}

// ============================================================================
extern "C" void kernel_launch(void* const* d_in, const int* in_sizes, int n_in,
                              void* d_out, int out_size)
{
    (void)in_sizes; (void)n_in; (void)out_size;
    const float* X  = (const float*)d_in[0];
    const float* A  = (const float*)d_in[1];
    const float* B  = (const float*)d_in[2];
    const float* C  = (const float*)d_in[3];
    const float* r  = (const float*)d_in[4];
    const float* k  = (const float*)d_in[5];
    const float* v  = (const float*)d_in[6];
    const float* w  = (const float*)d_in[7];
    const float* bo = (const float*)d_in[8];
    float* out = (float*)d_out;

    const int FUSED_SMEM = (2 * 64 * 65 + 64 * 64 + 3 * 64) * 4;  // 50432 B
    cudaFuncSetAttribute(fused_kernel,
                         cudaFuncAttributeMaxDynamicSharedMemorySize, FUSED_SMEM);

    fused_kernel<<<1056, 256, FUSED_SMEM>>>(X, A, B, C, r, k, v, w, bo, out);
    scan_kernel<<<128, 1024>>>();
    ssd_off_kernel<<<1024, 256>>>(C, out);
}

// round 5
// speedup vs baseline: 1.5959x; 1.3145x over previous
#include <cuda_runtime.h>
#include <cstdint>
#include <cstddef>

typedef unsigned long long ull;

// Problem constants
// X:(2,2048,16,64) A:(2,2048,16) B,C:(2,2048,16,64)
// r,k,v,w,bonus:(32,2048,64)  out:(2,2048,1024) f32

// ---------------- device scratch (static globals; no allocation) ------------
__device__ float g_states[2*32*16*64*64];   // per-chunk states (b,c,h,p,n)
__device__ float g_R[2*32*16*64*64];        // prefix state entering chunk c
__device__ float g_eA[1024*64];             // exp(cumA[l]) per (b,c,h)
__device__ float g_expsA[32*32];            // exp(chunk-sum A) per (b,h,c)
__device__ float g_yd[2*2048*1024];         // SSD Y_diag scratch

// ---------------- cp.async + f32x2 helpers -----------------------------------
__device__ __forceinline__ void cp_async16(float* dst, const float* src) {
    unsigned s = (unsigned)__cvta_generic_to_shared(dst);
    asm volatile("cp.async.cg.shared.global [%0], [%1], 16;\n" :: "r"(s), "l"(src));
}
__device__ __forceinline__ void cp_commit() { asm volatile("cp.async.commit_group;\n"); }
__device__ __forceinline__ void cp_wait1()  { asm volatile("cp.async.wait_group 1;\n" ::: "memory"); }
__device__ __forceinline__ void cp_wait0()  { asm volatile("cp.async.wait_group 0;\n" ::: "memory"); }

__device__ __forceinline__ ull f2fma(ull a, ull b, ull c) {
    ull d; asm("fma.rn.f32x2 %0, %1, %2, %3;" : "=l"(d) : "l"(a), "l"(b), "l"(c)); return d;
}
__device__ __forceinline__ ull f2mul(ull a, ull b) {
    ull d; asm("mul.rn.f32x2 %0, %1, %2;" : "=l"(d) : "l"(a), "l"(b)); return d;
}
__device__ __forceinline__ ull f2add(ull a, ull b) {
    ull d; asm("add.rn.f32x2 %0, %1, %2;" : "=l"(d) : "l"(a), "l"(b)); return d;
}
__device__ __forceinline__ ull pk2(float lo, float hi) {
    ull r; asm("mov.b64 %0, {%1, %2};" : "=l"(r) : "f"(lo), "f"(hi)); return r;
}
__device__ __forceinline__ float2 upk2(ull p) {
    float2 f; asm("mov.b64 {%0, %1}, %2;" : "=f"(f.x), "=f"(f.y) : "l"(p)); return f;
}

// ============================================================================
// WKV body: one CTA per batch-head, 256 threads.
// thread t = (i = t>>2, jq = t&3): row i, columns [jq*16, jq*16+16)
// Deferred-decay form: S~ = S / diag(W),  W_i = prod of w_i since window start.
// Per step (sequential part only):
//   u_i   = W_i * (S~ k)_i          (dot + 2 shfl)
//   delta_i = v_i - u_i             (computed ONCE by the row owner)
//   W_i  *= w_i
//   S~[i,j] += (b_i k_i / W_i) * delta_j     (pure outer product, 8 f2fma)
// Window epilogue: S~ <- diag(W) S~, W=1;  dk/y batched.
// smem: s_in[2][5][16][64] + s_dl[16][64] + s_dk[16]
// ============================================================================
__device__ __forceinline__ void wkv_block(
    int bh, int tid, float* sm,
    const float* __restrict__ rr, const float* __restrict__ kk_g,
    const float* __restrict__ vv_g, const float* __restrict__ ww_g,
    const float* __restrict__ bo_g, float* __restrict__ out)
{
    float* s_in = sm;             // [2][5][16][64] = 10240 floats
    float* s_dl = sm + 10240;     // [16][64]  delta per step
    float* s_dk = sm + 11264;     // [16]

    const int b = bh >> 4, h = bh & 15;
    const int i  = tid >> 2;
    const int jq = tid & 3;
    const int jb = jq * 16;
    const size_t base = (size_t)bh * 2048 * 64;
    const float* arrs[5] = { rr, kk_g, vv_g, ww_g, bo_g };
    const int st_ld  = tid >> 4;
    const int off_ld = (tid & 15) * 4;
    const int lane = tid & 31, wid = tid >> 5;

    ull S2[8];
#pragma unroll
    for (int u = 0; u < 8; ++u) S2[u] = 0ull;
    float W = 1.f;

#pragma unroll
    for (int wv = 0; wv < 2; ++wv) {
#pragma unroll
        for (int a = 0; a < 5; ++a)
            cp_async16(&s_in[(wv * 5 + a) * 1024 + st_ld * 64 + off_ld],
                       arrs[a] + base + (size_t)(wv * 16 + st_ld) * 64 + off_ld);
        cp_commit();
    }

#pragma unroll 1
    for (int win = 0; win < 128; ++win) {
        const int buf = win & 1;
        if (win >= 126) cp_wait0(); else cp_wait1();
        __syncthreads();
        const float* pr = s_in + buf * 5120;   // [5][16][64]

        // ---------------- sequential recurrence (lean) ----------------
#pragma unroll 2
        for (int st = 0; st < 16; ++st) {
            const float* kk_s = pr + 1024 + st * 64;

            // k for my 16 columns
            ull k2[8];
            {
                float4 q0 = *(const float4*)(kk_s + jb + 0);
                float4 q1 = *(const float4*)(kk_s + jb + 4);
                float4 q2 = *(const float4*)(kk_s + jb + 8);
                float4 q3 = *(const float4*)(kk_s + jb + 12);
                k2[0] = *(ull*)&q0.x; k2[1] = *(ull*)&q0.z;
                k2[2] = *(ull*)&q1.x; k2[3] = *(ull*)&q1.z;
                k2[4] = *(ull*)&q2.x; k2[5] = *(ull*)&q2.z;
                k2[6] = *(ull*)&q3.x; k2[7] = *(ull*)&q3.z;
            }

            // (S~ k) partial dot (4 independent packed chains, tree reduce)
            ull a0 = f2mul(S2[0], k2[0]);
            ull a1 = f2mul(S2[1], k2[1]);
            ull a2 = f2mul(S2[2], k2[2]);
            ull a3 = f2mul(S2[3], k2[3]);
            a0 = f2fma(S2[4], k2[4], a0);
            a1 = f2fma(S2[5], k2[5], a1);
            a2 = f2fma(S2[6], k2[6], a2);
            a3 = f2fma(S2[7], k2[7], a3);
            a0 = f2add(a0, a1); a2 = f2add(a2, a3); a0 = f2add(a0, a2);
            float2 af = upk2(a0);
            float acc = af.x + af.y;
            acc += __shfl_xor_sync(0xffffffffu, acc, 1);
            acc += __shfl_xor_sync(0xffffffffu, acc, 2);

            // row-owner computes delta_i = v_i - W*(S~k)_i once; all quad
            // lanes hold the same value -> redundant same-address store (no branch)
            const float vi = pr[2048 + st * 64 + i];
            const float di = vi - W * acc;
            s_dl[st * 64 + i] = di;

            const float wi = pr[3072 + st * 64 + i];
            const float ki = kk_s[i];
            const float bi = pr[4096 + st * 64 + i];
            W *= wi;
            const float ci = __fdividef(bi * ki, W);
            const ull c2 = pk2(ci, ci);
            __syncthreads();

            // outer-product update: S~ += c * delta (4 LDS.128 + 8 f2fma)
            ull d2[8];
#pragma unroll
            for (int q = 0; q < 4; ++q) {
                float4 dq = *(const float4*)(s_dl + st * 64 + jb + 4 * q);
                d2[2 * q]     = *(ull*)&dq.x;
                d2[2 * q + 1] = *(ull*)&dq.z;
            }
#pragma unroll
            for (int u = 0; u < 8; ++u) S2[u] = f2fma(c2, d2[u], S2[u]);
        }

        // ---------------- window epilogue: rescale S~ <- diag(W) S~ --------
        {
            const ull w2 = pk2(W, W);
#pragma unroll
            for (int u = 0; u < 8; ++u) S2[u] = f2mul(S2[u], w2);
            W = 1.f;
        }

        // ---------------- dk[st] = delta . k : warp-dots ----------------
#pragma unroll
        for (int rep = 0; rep < 2; ++rep) {
            const int st = wid + rep * 8;
            const float* kk_s = pr + 1024 + st * 64;
            const float* dl_s = s_dl + st * 64;
            float2 kv = *(const float2*)(kk_s + lane * 2);
            float2 dl2 = *(const float2*)(dl_s + lane * 2);
            float pd = fmaf(dl2.x, kv.x, dl2.y * kv.y);
#pragma unroll
            for (int off = 16; off > 0; off >>= 1)
                pd += __shfl_xor_sync(0xffffffffu, pd, off);
            if (lane == 0) s_dk[st] = pd;
        }
        __syncthreads();

        // ---------------- batched y: coalesced stores ----------------
        // Sk_i = v_i - delta_i ; y = r*(w*Sk + b*k*dk)
#pragma unroll
        for (int u = 0; u < 4; ++u) {
            const int idx = u * 256 + tid;      // 0..1023
            const int st = idx >> 6, ii = idx & 63;
            const float dl = s_dl[st * 64 + ii];
            const float r_ = pr[st * 64 + ii];
            const float k_ = pr[1024 + st * 64 + ii];
            const float v_ = pr[2048 + st * 64 + ii];
            const float w_ = pr[3072 + st * 64 + ii];
            const float b_ = pr[4096 + st * 64 + ii];
            const float dk = s_dk[st];
            const float y = r_ * fmaf(b_ * k_, dk, w_ * (v_ - dl));
            out[(size_t)(b * 2048 + win * 16 + st) * 1024 + h * 64 + ii] = y;
        }
        __syncthreads();   // all reads of buf done before refill

        if (win + 2 < 128) {
#pragma unroll
            for (int a = 0; a < 5; ++a)
                cp_async16(&s_in[(buf * 5 + a) * 1024 + st_ld * 64 + off_ld],
                           arrs[a] + base + (size_t)((win + 2) * 16 + st_ld) * 64 + off_ld);
            cp_commit();
        }
    }
}

// ============================================================================
// SSD per-chunk body (writes Y_diag to g_yd; states to g_states)
// smem: sB[64][65], sG[64][65], sX[64][64], cum/eA/ieA[64] = 50432 bytes
// ============================================================================
__device__ __forceinline__ void ssd_chunk_body(
    int blk, int tid, float* sm,
    const float* __restrict__ X, const float* __restrict__ A,
    const float* __restrict__ Bm, const float* __restrict__ Cm)
{
    float* sB   = sm;
    float* sG   = sm + 64 * 65;
    float* sX   = sm + 2 * 64 * 65;
    float* s_cum = sX + 4096;
    float* s_eA  = s_cum + 64;
    float* s_ieA = s_eA + 64;

    const int h  = blk & 15;
    const int cc = (blk >> 4) & 31;
    const int b  = blk >> 9;

    const size_t gbase = ((size_t)(b * 2048 + cc * 64) * 16 + h) * 64;
#pragma unroll
    for (int u = 0; u < 4; ++u) {
        int idx4 = u * 256 + tid;
        int l = idx4 >> 4, n4 = (idx4 & 15) * 4;
        size_t go = gbase + (size_t)l * 1024 + n4;
        float4 bv = *(const float4*)(Bm + go);
        float4 cv = *(const float4*)(Cm + go);
        float4 xv = *(const float4*)(X + go);
        float* pb = sB + l * 65 + n4;
        pb[0] = bv.x; pb[1] = bv.y; pb[2] = bv.z; pb[3] = bv.w;
        float* pc = sG + l * 65 + n4;
        pc[0] = cv.x; pc[1] = cv.y; pc[2] = cv.z; pc[3] = cv.w;
        *(float4*)(sX + l * 64 + n4) = xv;
    }
    if (tid < 64) {
        float x = A[(size_t)(b * 2048 + cc * 64 + tid) * 16 + h];
#pragma unroll
        for (int o = 1; o < 32; o <<= 1) {
            float t = __shfl_up_sync(0xffffffffu, x, o);
            if ((tid & 31) >= o) x += t;
        }
        s_cum[tid] = x;
    }
    __syncthreads();
    if (tid < 64) {
        float x = s_cum[tid] + ((tid >= 32) ? s_cum[31] : 0.f);
        float e = expf(x);
        s_eA[tid]  = e;
        s_ieA[tid] = expf(-x);
        g_eA[(size_t)blk * 64 + tid] = e;
        if (tid == 63) g_expsA[(b * 16 + h) * 32 + cc] = e;
    }
    __syncthreads();

    const int tl = tid >> 4, ts = tid & 15;
    const int r0 = tl * 4, c0 = ts * 4;

    // G = dot(C_l, B_s)
    float g[4][4];
#pragma unroll
    for (int ii = 0; ii < 4; ++ii)
#pragma unroll
        for (int jj = 0; jj < 4; ++jj) g[ii][jj] = 0.f;
    for (int n = 0; n < 64; ++n) {
        float cl[4], bsv[4];
#pragma unroll
        for (int ii = 0; ii < 4; ++ii) cl[ii] = sG[(r0 + ii) * 65 + n];
#pragma unroll
        for (int jj = 0; jj < 4; ++jj) bsv[jj] = sB[(c0 + jj) * 65 + n];
#pragma unroll
        for (int ii = 0; ii < 4; ++ii)
#pragma unroll
            for (int jj = 0; jj < 4; ++jj) g[ii][jj] = fmaf(cl[ii], bsv[jj], g[ii][jj]);
    }
    __syncthreads();
#pragma unroll
    for (int ii = 0; ii < 4; ++ii) {
        int l = r0 + ii;
        float el = s_eA[l];
#pragma unroll
        for (int jj = 0; jj < 4; ++jj) {
            int s = c0 + jj;
            sG[l * 65 + s] = (s <= l) ? g[ii][jj] * el * s_ieA[s] : 0.f;
        }
    }
    __syncthreads();

    // Y_diag
    float y[4][4];
#pragma unroll
    for (int ii = 0; ii < 4; ++ii)
#pragma unroll
        for (int jj = 0; jj < 4; ++jj) y[ii][jj] = 0.f;
    for (int s = 0; s < 64; ++s) {
        float4 xv = *(const float4*)(sX + s * 64 + c0);
        float gl[4];
#pragma unroll
        for (int ii = 0; ii < 4; ++ii) gl[ii] = sG[(r0 + ii) * 65 + s];
#pragma unroll
        for (int ii = 0; ii < 4; ++ii) {
            y[ii][0] = fmaf(gl[ii], xv.x, y[ii][0]);
            y[ii][1] = fmaf(gl[ii], xv.y, y[ii][1]);
            y[ii][2] = fmaf(gl[ii], xv.z, y[ii][2]);
            y[ii][3] = fmaf(gl[ii], xv.w, y[ii][3]);
        }
    }
#pragma unroll
    for (int ii = 0; ii < 4; ++ii) {
        int l = r0 + ii;
        *(float4*)(g_yd + (size_t)(b * 2048 + cc * 64 + l) * 1024 + h * 64 + c0) =
            make_float4(y[ii][0], y[ii][1], y[ii][2], y[ii][3]);
    }

    // chunk states
    float stt[4][4];
#pragma unroll
    for (int ii = 0; ii < 4; ++ii)
#pragma unroll
        for (int jj = 0; jj < 4; ++jj) stt[ii][jj] = 0.f;
    const float eA63 = s_eA[63];
    for (int l = 0; l < 64; ++l) {
        float ds = eA63 * s_ieA[l];
        float4 xv = *(const float4*)(sX + l * 64 + r0);
        float xw[4] = { xv.x * ds, xv.y * ds, xv.z * ds, xv.w * ds };
        float bv[4];
#pragma unroll
        for (int jj = 0; jj < 4; ++jj) bv[jj] = sB[l * 65 + c0 + jj];
#pragma unroll
        for (int ii = 0; ii < 4; ++ii)
#pragma unroll
            for (int jj = 0; jj < 4; ++jj) stt[ii][jj] = fmaf(xw[ii], bv[jj], stt[ii][jj]);
    }
#pragma unroll
    for (int ii = 0; ii < 4; ++ii)
        *(float4*)(g_states + (size_t)blk * 4096 + (size_t)(r0 + ii) * 64 + c0) =
            make_float4(stt[ii][0], stt[ii][1], stt[ii][2], stt[ii][3]);
}

// ============================================================================
// Fused: blockIdx 0..31 -> WKV (long), 32..1055 -> SSD chunk (overlapped)
// ============================================================================
__global__ void __launch_bounds__(256, 2) fused_kernel(
    const float* __restrict__ X, const float* __restrict__ A,
    const float* __restrict__ Bm, const float* __restrict__ Cm,
    const float* __restrict__ rr, const float* __restrict__ kk,
    const float* __restrict__ vv, const float* __restrict__ ww,
    const float* __restrict__ bo, float* __restrict__ out)
{
    extern __shared__ float sm[];
    if (blockIdx.x < 32) {
        wkv_block(blockIdx.x, threadIdx.x, sm, rr, kk, vv, ww, bo, out);
    } else {
        ssd_chunk_body(blockIdx.x - 32, threadIdx.x, sm, X, A, Bm, Cm);
    }
}

// ============================================================================
// K2: inter-chunk decay scan
// ============================================================================
__global__ void __launch_bounds__(1024) scan_kernel()
{
    const int bid = blockIdx.x;
    const int bh = bid >> 2, q = bid & 3;
    const int b = bh >> 4, h = bh & 15;
    const int e = q * 1024 + threadIdx.x;
    float R = 0.f;
    const float* es = g_expsA + bh * 32;
#pragma unroll 1
    for (int c = 0; c < 32; ++c) {
        size_t idx = (size_t)(b * 512 + c * 16 + h) * 4096 + e;
        g_R[idx] = R;
        R = fmaf(R, es[c], g_states[idx]);
    }
}

// ============================================================================
// K3: out += g_yd + eA[l] * (C . R^T)
// ============================================================================
__global__ void __launch_bounds__(256) ssd_off_kernel(
    const float* __restrict__ Cm, float* __restrict__ out)
{
    __shared__ float sC[64 * 65];
    __shared__ float sR[64 * 65];
    __shared__ float s_e[64];
    const int blk = blockIdx.x;
    const int h  = blk & 15;
    const int cc = (blk >> 4) & 31;
    const int b  = blk >> 9;
    const int tid = threadIdx.x;

    const size_t gbase = ((size_t)(b * 2048 + cc * 64) * 16 + h) * 64;
#pragma unroll
    for (int u = 0; u < 4; ++u) {
        int idx4 = u * 256 + tid;
        int l = idx4 >> 4, n4 = (idx4 & 15) * 4;
        float4 cv = *(const float4*)(Cm + gbase + (size_t)l * 1024 + n4);
        float4 rv = *(const float4*)(g_R + (size_t)blk * 4096 + (size_t)idx4 * 4);
        float* pc = sC + l * 65 + n4;
        pc[0] = cv.x; pc[1] = cv.y; pc[2] = cv.z; pc[3] = cv.w;
        float* pr = sR + l * 65 + n4;
        pr[0] = rv.x; pr[1] = rv.y; pr[2] = rv.z; pr[3] = rv.w;
    }
    if (tid < 64) s_e[tid] = g_eA[(size_t)blk * 64 + tid];
    __syncthreads();

    const int tl = tid >> 4, ts = tid & 15;
    const int l0 = tl * 4, p0 = ts * 4;

    float acc[4][4];
#pragma unroll
    for (int ii = 0; ii < 4; ++ii)
#pragma unroll
        for (int jj = 0; jj < 4; ++jj) acc[ii][jj] = 0.f;

    for (int n = 0; n < 64; ++n) {
        float cl[4], rv[4];
#pragma unroll
        for (int ii = 0; ii < 4; ++ii) cl[ii] = sC[(l0 + ii) * 65 + n];
#pragma unroll
        for (int jj = 0; jj < 4; ++jj) rv[jj] = sR[(p0 + jj) * 65 + n];
#pragma unroll
        for (int ii = 0; ii < 4; ++ii)
#pragma unroll
            for (int jj = 0; jj < 4; ++jj) acc[ii][jj] = fmaf(cl[ii], rv[jj], acc[ii][jj]);
    }
#pragma unroll
    for (int ii = 0; ii < 4; ++ii) {
        int l = l0 + ii;
        float e = s_e[l];
        size_t ofs = (size_t)(b * 2048 + cc * 64 + l) * 1024 + h * 64 + p0;
        float4* po = (float4*)(out + ofs);
        float4 o  = *po;
        float4 yd = *(const float4*)(g_yd + ofs);
        o.x += yd.x + e * acc[ii][0];
        o.y += yd.y + e * acc[ii][1];
        o.z += yd.z + e * acc[ii][2];
        o.w += yd.w + e * acc[ii][3];
        *po = o;
    }
}

// ============================================================================
extern "C" void kernel_launch(void* const* d_in, const int* in_sizes, int n_in,
                              void* d_out, int out_size)
{
    (void)in_sizes; (void)n_in; (void)out_size;
    const float* X  = (const float*)d_in[0];
    const float* A  = (const float*)d_in[1];
    const float* B  = (const float*)d_in[2];
    const float* C  = (const float*)d_in[3];
    const float* r  = (const float*)d_in[4];
    const float* k  = (const float*)d_in[5];
    const float* v  = (const float*)d_in[6];
    const float* w  = (const float*)d_in[7];
    const float* bo = (const float*)d_in[8];
    float* out = (float*)d_out;

    const int FUSED_SMEM = (2 * 64 * 65 + 64 * 64 + 3 * 64) * 4;  // 50432 B
    cudaFuncSetAttribute(fused_kernel,
                         cudaFuncAttributeMaxDynamicSharedMemorySize, FUSED_SMEM);

    fused_kernel<<<1056, 256, FUSED_SMEM>>>(X, A, B, C, r, k, v, w, bo, out);
    scan_kernel<<<128, 1024>>>();
    ssd_off_kernel<<<1024, 256>>>(C, out);
}

// round 6
// speedup vs baseline: 2.4946x; 1.5632x over previous
#include <cuda_runtime.h>
#include <cstdint>
#include <cstddef>

typedef unsigned long long ull;

// Problem constants
// X:(2,2048,16,64) A:(2,2048,16) B,C:(2,2048,16,64)
// r,k,v,w,bonus:(32,2048,64)  out:(2,2048,1024) f32

// ---------------- device scratch (static globals; no allocation) ------------
__device__ float g_states[2*32*16*64*64];   // per-chunk states (b,c,h,p,n)
__device__ float g_R[2*32*16*64*64];        // prefix state entering chunk c
__device__ float g_eA[1024*64];             // exp(cumA[l]) per (b,c,h)
__device__ float g_expsA[32*32];            // exp(chunk-sum A) per (b,h,c)
__device__ float g_yd[2*2048*1024];         // SSD Y_diag scratch

// ---------------- cp.async + f32x2 helpers -----------------------------------
__device__ __forceinline__ void cp_async16(float* dst, const float* src) {
    unsigned s = (unsigned)__cvta_generic_to_shared(dst);
    asm volatile("cp.async.cg.shared.global [%0], [%1], 16;\n" :: "r"(s), "l"(src));
}
__device__ __forceinline__ void cp_commit() { asm volatile("cp.async.commit_group;\n"); }
__device__ __forceinline__ void cp_wait1()  { asm volatile("cp.async.wait_group 1;\n" ::: "memory"); }
__device__ __forceinline__ void cp_wait0()  { asm volatile("cp.async.wait_group 0;\n" ::: "memory"); }

__device__ __forceinline__ ull f2fma(ull a, ull b, ull c) {
    ull d; asm("fma.rn.f32x2 %0, %1, %2, %3;" : "=l"(d) : "l"(a), "l"(b), "l"(c)); return d;
}
__device__ __forceinline__ ull f2mul(ull a, ull b) {
    ull d; asm("mul.rn.f32x2 %0, %1, %2;" : "=l"(d) : "l"(a), "l"(b)); return d;
}
__device__ __forceinline__ ull f2add(ull a, ull b) {
    ull d; asm("add.rn.f32x2 %0, %1, %2;" : "=l"(d) : "l"(a), "l"(b)); return d;
}
__device__ __forceinline__ ull pk2(float lo, float hi) {
    ull r; asm("mov.b64 %0, {%1, %2};" : "=l"(r) : "f"(lo), "f"(hi)); return r;
}
__device__ __forceinline__ float2 upk2(ull p) {
    float2 f; asm("mov.b64 {%0, %1}, %2;" : "=f"(f.x), "=f"(f.y) : "l"(p)); return f;
}

// Chunk swizzle for 64-float rows read as (h2, u) 16B chunks:
// logical chunk c = h2*8+u  ->  physical chunk u*2+h2.
// Guarantees the two chunks touched by one LDS.128 (u fixed, h2=0/1) occupy
// disjoint banks -> 1 wavefront per LDS.128.
__device__ __forceinline__ int swz_chunk(int c) { return ((c & 7) << 1) | (c >> 3); }
__device__ __forceinline__ int swz_pos(int j)   { return (swz_chunk(j >> 2) << 2) | (j & 3); }

#define WKV_BAR() asm volatile("bar.sync 1, 128;" ::: "memory")

// ============================================================================
// WKV body: one CTA per batch-head, 128 active threads.
// thread t = (i = t>>1, h2 = t&1): row i, columns [h2*32, h2*32+32)
// Deferred-decay form: S~ = S / W_i.
// Per step: acc=(S~k)_i [dot + 1 shfl]; delta_i = v_i - W*acc (stored swizzled);
//           W*=w_i; S~ += (b_i k_i / W) * delta   [after one barrier]
// k array stored swizzled (at cp.async), delta stored swizzled.
// ============================================================================
__device__ __forceinline__ void wkv_block(
    int bh, int tid, float* sm,
    const float* __restrict__ rr, const float* __restrict__ kk_g,
    const float* __restrict__ vv_g, const float* __restrict__ ww_g,
    const float* __restrict__ bo_g, float* __restrict__ out)
{
    float* s_in = sm;             // [2][5][16][64] = 10240 floats
    float* s_dl = sm + 10240;     // [16][64]  delta per step (swizzled)
    float* s_dk = sm + 11264;     // [16]

    const int b = bh >> 4, h = bh & 15;
    const int i  = tid >> 1;          // row 0..63
    const int h2 = tid & 1;           // column half
    const size_t base = (size_t)bh * 2048 * 64;
    const float* arrs[5] = { rr, kk_g, vv_g, ww_g, bo_g };
    const int st_ld = tid >> 3;       // 0..15 step for loads
    const int ch_ld = tid & 7;        // chunk 0..7 (and +8)
    const int lane = tid & 31, wid = tid >> 5;
    const int pos_i = swz_pos(i);     // swizzled scalar slot for row i

    ull S2[16];
#pragma unroll
    for (int u = 0; u < 16; ++u) S2[u] = 0ull;
    float W = 1.f;

    // prefetch windows 0 and 1 (k array = a==1 stored swizzled)
#pragma unroll
    for (int wv = 0; wv < 2; ++wv) {
#pragma unroll
        for (int a = 0; a < 5; ++a)
#pragma unroll
            for (int rep = 0; rep < 2; ++rep) {
                int c = rep * 8 + ch_ld;
                int dc = (a == 1) ? swz_chunk(c) : c;
                cp_async16(&s_in[(wv * 5 + a) * 1024 + st_ld * 64 + dc * 4],
                           arrs[a] + base + (size_t)(wv * 16 + st_ld) * 64 + c * 4);
            }
        cp_commit();
    }

#pragma unroll 1
    for (int win = 0; win < 128; ++win) {
        const int buf = win & 1;
        if (win >= 126) cp_wait0(); else cp_wait1();
        WKV_BAR();
        const float* pr = s_in + buf * 5120;   // [5][16][64]

        // ---------------- sequential recurrence ----------------
#pragma unroll 1
        for (int st = 0; st < 16; ++st) {
            const float* kk_s = pr + 1024 + st * 64;   // swizzled k row

            // k for my 32 columns: 8 conflict-free LDS.128
            ull k2[16];
#pragma unroll
            for (int u = 0; u < 8; ++u) {
                float4 q = *(const float4*)(kk_s + (2 * u + h2) * 4);
                k2[2 * u]     = *(ull*)&q.x;
                k2[2 * u + 1] = *(ull*)&q.z;
            }

            // (S~ k) partial: 4 independent packed chains, tree reduce
            ull a0 = f2mul(S2[0], k2[0]);
            ull a1 = f2mul(S2[1], k2[1]);
            ull a2 = f2mul(S2[2], k2[2]);
            ull a3 = f2mul(S2[3], k2[3]);
#pragma unroll
            for (int u = 1; u < 4; ++u) {
                a0 = f2fma(S2[4 * u + 0], k2[4 * u + 0], a0);
                a1 = f2fma(S2[4 * u + 1], k2[4 * u + 1], a1);
                a2 = f2fma(S2[4 * u + 2], k2[4 * u + 2], a2);
                a3 = f2fma(S2[4 * u + 3], k2[4 * u + 3], a3);
            }
            a0 = f2add(a0, a1); a2 = f2add(a2, a3); a0 = f2add(a0, a2);
            float2 af = upk2(a0);
            float acc = af.x + af.y;
            acc += __shfl_xor_sync(0xffffffffu, acc, 1);   // pair = other half

            // row scalars (broadcast loads)
            const float vi = pr[2048 + st * 64 + i];
            const float wi = pr[3072 + st * 64 + i];
            const float bi = pr[4096 + st * 64 + i];
            const float ki = kk_s[pos_i];

            const float di = vi - W * acc;
            s_dl[st * 64 + pos_i] = di;      // both lanes store same value
            W *= wi;
            const float ci = __fdividef(bi * ki, W);
            const ull c2 = pk2(ci, ci);
            WKV_BAR();

            // outer-product update: 8 conflict-free LDS.128 + 16 f2fma
#pragma unroll
            for (int u = 0; u < 8; ++u) {
                float4 dq = *(const float4*)(s_dl + st * 64 + (2 * u + h2) * 4);
                S2[2 * u]     = f2fma(c2, *(ull*)&dq.x, S2[2 * u]);
                S2[2 * u + 1] = f2fma(c2, *(ull*)&dq.z, S2[2 * u + 1]);
            }
        }

        // window epilogue: rescale S~ <- diag(W) S~
        {
            const ull w2 = pk2(W, W);
#pragma unroll
            for (int u = 0; u < 16; ++u) S2[u] = f2mul(S2[u], w2);
            W = 1.f;
        }

        // ---------------- dk[st] = delta . k : warp-dots ----------------
#pragma unroll
        for (int rep = 0; rep < 4; ++rep) {
            const int st = rep * 4 + wid;
            const int pp = swz_chunk(lane >> 1) * 4 + (lane & 1) * 2;
            float2 kv  = *(const float2*)(pr + 1024 + st * 64 + pp);
            float2 dl2 = *(const float2*)(s_dl + st * 64 + pp);
            float pd = fmaf(dl2.x, kv.x, dl2.y * kv.y);
#pragma unroll
            for (int off = 16; off > 0; off >>= 1)
                pd += __shfl_xor_sync(0xffffffffu, pd, off);
            if (lane == 0) s_dk[st] = pd;
        }
        WKV_BAR();

        // ---------------- batched y: float2 stores ----------------
        // Sk = v - delta ; y = r*(w*Sk + b*k*dk)
#pragma unroll
        for (int rep = 0; rep < 4; ++rep) {
            const int idx = rep * 128 + tid;        // 0..511 (st, colpair)
            const int st = idx >> 5, cp2 = idx & 31;
            const int col = cp2 * 2;
            const int pp = swz_chunk(cp2 >> 1) * 4 + (cp2 & 1) * 2;
            float2 dl = *(const float2*)(s_dl + st * 64 + pp);
            float2 k_ = *(const float2*)(pr + 1024 + st * 64 + pp);
            float2 r_ = *(const float2*)(pr + st * 64 + col);
            float2 v_ = *(const float2*)(pr + 2048 + st * 64 + col);
            float2 w_ = *(const float2*)(pr + 3072 + st * 64 + col);
            float2 b_ = *(const float2*)(pr + 4096 + st * 64 + col);
            const float dk = s_dk[st];
            float2 y;
            y.x = r_.x * fmaf(b_.x * k_.x, dk, w_.x * (v_.x - dl.x));
            y.y = r_.y * fmaf(b_.y * k_.y, dk, w_.y * (v_.y - dl.y));
            *(float2*)(out + (size_t)(b * 2048 + win * 16 + st) * 1024 + h * 64 + col) = y;
        }
        WKV_BAR();   // all reads of buf done before refill

        if (win + 2 < 128) {
#pragma unroll
            for (int a = 0; a < 5; ++a)
#pragma unroll
                for (int rep = 0; rep < 2; ++rep) {
                    int c = rep * 8 + ch_ld;
                    int dc = (a == 1) ? swz_chunk(c) : c;
                    cp_async16(&s_in[(buf * 5 + a) * 1024 + st_ld * 64 + dc * 4],
                               arrs[a] + base + (size_t)((win + 2) * 16 + st_ld) * 64 + c * 4);
                }
            cp_commit();
        }
    }
}

// ============================================================================
// SSD per-chunk body (writes Y_diag to g_yd; states to g_states)
// smem: sB[64][65], sG[64][65], sX[64][64], cum/eA/ieA[64] = 50432 bytes
// ============================================================================
__device__ __forceinline__ void ssd_chunk_body(
    int blk, int tid, float* sm,
    const float* __restrict__ X, const float* __restrict__ A,
    const float* __restrict__ Bm, const float* __restrict__ Cm)
{
    float* sB   = sm;
    float* sG   = sm + 64 * 65;
    float* sX   = sm + 2 * 64 * 65;
    float* s_cum = sX + 4096;
    float* s_eA  = s_cum + 64;
    float* s_ieA = s_eA + 64;

    const int h  = blk & 15;
    const int cc = (blk >> 4) & 31;
    const int b  = blk >> 9;

    const size_t gbase = ((size_t)(b * 2048 + cc * 64) * 16 + h) * 64;
#pragma unroll
    for (int u = 0; u < 4; ++u) {
        int idx4 = u * 256 + tid;
        int l = idx4 >> 4, n4 = (idx4 & 15) * 4;
        size_t go = gbase + (size_t)l * 1024 + n4;
        float4 bv = *(const float4*)(Bm + go);
        float4 cv = *(const float4*)(Cm + go);
        float4 xv = *(const float4*)(X + go);
        float* pb = sB + l * 65 + n4;
        pb[0] = bv.x; pb[1] = bv.y; pb[2] = bv.z; pb[3] = bv.w;
        float* pc = sG + l * 65 + n4;
        pc[0] = cv.x; pc[1] = cv.y; pc[2] = cv.z; pc[3] = cv.w;
        *(float4*)(sX + l * 64 + n4) = xv;
    }
    if (tid < 64) {
        float x = A[(size_t)(b * 2048 + cc * 64 + tid) * 16 + h];
#pragma unroll
        for (int o = 1; o < 32; o <<= 1) {
            float t = __shfl_up_sync(0xffffffffu, x, o);
            if ((tid & 31) >= o) x += t;
        }
        s_cum[tid] = x;
    }
    __syncthreads();
    if (tid < 64) {
        float x = s_cum[tid] + ((tid >= 32) ? s_cum[31] : 0.f);
        float e = expf(x);
        s_eA[tid]  = e;
        s_ieA[tid] = expf(-x);
        g_eA[(size_t)blk * 64 + tid] = e;
        if (tid == 63) g_expsA[(b * 16 + h) * 32 + cc] = e;
    }
    __syncthreads();

    const int tl = tid >> 4, ts = tid & 15;
    const int r0 = tl * 4, c0 = ts * 4;

    // G = dot(C_l, B_s)
    float g[4][4];
#pragma unroll
    for (int ii = 0; ii < 4; ++ii)
#pragma unroll
        for (int jj = 0; jj < 4; ++jj) g[ii][jj] = 0.f;
    for (int n = 0; n < 64; ++n) {
        float cl[4], bsv[4];
#pragma unroll
        for (int ii = 0; ii < 4; ++ii) cl[ii] = sG[(r0 + ii) * 65 + n];
#pragma unroll
        for (int jj = 0; jj < 4; ++jj) bsv[jj] = sB[(c0 + jj) * 65 + n];
#pragma unroll
        for (int ii = 0; ii < 4; ++ii)
#pragma unroll
            for (int jj = 0; jj < 4; ++jj) g[ii][jj] = fmaf(cl[ii], bsv[jj], g[ii][jj]);
    }
    __syncthreads();
#pragma unroll
    for (int ii = 0; ii < 4; ++ii) {
        int l = r0 + ii;
        float el = s_eA[l];
#pragma unroll
        for (int jj = 0; jj < 4; ++jj) {
            int s = c0 + jj;
            sG[l * 65 + s] = (s <= l) ? g[ii][jj] * el * s_ieA[s] : 0.f;
        }
    }
    __syncthreads();

    // Y_diag
    float y[4][4];
#pragma unroll
    for (int ii = 0; ii < 4; ++ii)
#pragma unroll
        for (int jj = 0; jj < 4; ++jj) y[ii][jj] = 0.f;
    for (int s = 0; s < 64; ++s) {
        float4 xv = *(const float4*)(sX + s * 64 + c0);
        float gl[4];
#pragma unroll
        for (int ii = 0; ii < 4; ++ii) gl[ii] = sG[(r0 + ii) * 65 + s];
#pragma unroll
        for (int ii = 0; ii < 4; ++ii) {
            y[ii][0] = fmaf(gl[ii], xv.x, y[ii][0]);
            y[ii][1] = fmaf(gl[ii], xv.y, y[ii][1]);
            y[ii][2] = fmaf(gl[ii], xv.z, y[ii][2]);
            y[ii][3] = fmaf(gl[ii], xv.w, y[ii][3]);
        }
    }
#pragma unroll
    for (int ii = 0; ii < 4; ++ii) {
        int l = r0 + ii;
        *(float4*)(g_yd + (size_t)(b * 2048 + cc * 64 + l) * 1024 + h * 64 + c0) =
            make_float4(y[ii][0], y[ii][1], y[ii][2], y[ii][3]);
    }

    // chunk states
    float stt[4][4];
#pragma unroll
    for (int ii = 0; ii < 4; ++ii)
#pragma unroll
        for (int jj = 0; jj < 4; ++jj) stt[ii][jj] = 0.f;
    const float eA63 = s_eA[63];
    for (int l = 0; l < 64; ++l) {
        float ds = eA63 * s_ieA[l];
        float4 xv = *(const float4*)(sX + l * 64 + r0);
        float xw[4] = { xv.x * ds, xv.y * ds, xv.z * ds, xv.w * ds };
        float bv[4];
#pragma unroll
        for (int jj = 0; jj < 4; ++jj) bv[jj] = sB[l * 65 + c0 + jj];
#pragma unroll
        for (int ii = 0; ii < 4; ++ii)
#pragma unroll
            for (int jj = 0; jj < 4; ++jj) stt[ii][jj] = fmaf(xw[ii], bv[jj], stt[ii][jj]);
    }
#pragma unroll
    for (int ii = 0; ii < 4; ++ii)
        *(float4*)(g_states + (size_t)blk * 4096 + (size_t)(r0 + ii) * 64 + c0) =
            make_float4(stt[ii][0], stt[ii][1], stt[ii][2], stt[ii][3]);
}

// ============================================================================
// Fused: blockIdx 0..31 -> WKV (128 active threads), 32..1055 -> SSD chunk
// ============================================================================
__global__ void __launch_bounds__(256, 2) fused_kernel(
    const float* __restrict__ X, const float* __restrict__ A,
    const float* __restrict__ Bm, const float* __restrict__ Cm,
    const float* __restrict__ rr, const float* __restrict__ kk,
    const float* __restrict__ vv, const float* __restrict__ ww,
    const float* __restrict__ bo, float* __restrict__ out)
{
    extern __shared__ float sm[];
    if (blockIdx.x < 32) {
        if (threadIdx.x >= 128) return;   // whole warps exit; frees slots
        wkv_block(blockIdx.x, threadIdx.x, sm, rr, kk, vv, ww, bo, out);
    } else {
        ssd_chunk_body(blockIdx.x - 32, threadIdx.x, sm, X, A, Bm, Cm);
    }
}

// ============================================================================
// K2: inter-chunk decay scan
// ============================================================================
__global__ void __launch_bounds__(1024) scan_kernel()
{
    const int bid = blockIdx.x;
    const int bh = bid >> 2, q = bid & 3;
    const int b = bh >> 4, h = bh & 15;
    const int e = q * 1024 + threadIdx.x;
    float R = 0.f;
    const float* es = g_expsA + bh * 32;
#pragma unroll 1
    for (int c = 0; c < 32; ++c) {
        size_t idx = (size_t)(b * 512 + c * 16 + h) * 4096 + e;
        g_R[idx] = R;
        R = fmaf(R, es[c], g_states[idx]);
    }
}

// ============================================================================
// K3: out += g_yd + eA[l] * (C . R^T)
// ============================================================================
__global__ void __launch_bounds__(256) ssd_off_kernel(
    const float* __restrict__ Cm, float* __restrict__ out)
{
    __shared__ float sC[64 * 65];
    __shared__ float sR[64 * 65];
    __shared__ float s_e[64];
    const int blk = blockIdx.x;
    const int h  = blk & 15;
    const int cc = (blk >> 4) & 31;
    const int b  = blk >> 9;
    const int tid = threadIdx.x;

    const size_t gbase = ((size_t)(b * 2048 + cc * 64) * 16 + h) * 64;
#pragma unroll
    for (int u = 0; u < 4; ++u) {
        int idx4 = u * 256 + tid;
        int l = idx4 >> 4, n4 = (idx4 & 15) * 4;
        float4 cv = *(const float4*)(Cm + gbase + (size_t)l * 1024 + n4);
        float4 rv = *(const float4*)(g_R + (size_t)blk * 4096 + (size_t)idx4 * 4);
        float* pc = sC + l * 65 + n4;
        pc[0] = cv.x; pc[1] = cv.y; pc[2] = cv.z; pc[3] = cv.w;
        float* pr = sR + l * 65 + n4;
        pr[0] = rv.x; pr[1] = rv.y; pr[2] = rv.z; pr[3] = rv.w;
    }
    if (tid < 64) s_e[tid] = g_eA[(size_t)blk * 64 + tid];
    __syncthreads();

    const int tl = tid >> 4, ts = tid & 15;
    const int l0 = tl * 4, p0 = ts * 4;

    float acc[4][4];
#pragma unroll
    for (int ii = 0; ii < 4; ++ii)
#pragma unroll
        for (int jj = 0; jj < 4; ++jj) acc[ii][jj] = 0.f;

    for (int n = 0; n < 64; ++n) {
        float cl[4], rv[4];
#pragma unroll
        for (int ii = 0; ii < 4; ++ii) cl[ii] = sC[(l0 + ii) * 65 + n];
#pragma unroll
        for (int jj = 0; jj < 4; ++jj) rv[jj] = sR[(p0 + jj) * 65 + n];
#pragma unroll
        for (int ii = 0; ii < 4; ++ii)
#pragma unroll
            for (int jj = 0; jj < 4; ++jj) acc[ii][jj] = fmaf(cl[ii], rv[jj], acc[ii][jj]);
    }
#pragma unroll
    for (int ii = 0; ii < 4; ++ii) {
        int l = l0 + ii;
        float e = s_e[l];
        size_t ofs = (size_t)(b * 2048 + cc * 64 + l) * 1024 + h * 64 + p0;
        float4* po = (float4*)(out + ofs);
        float4 o  = *po;
        float4 yd = *(const float4*)(g_yd + ofs);
        o.x += yd.x + e * acc[ii][0];
        o.y += yd.y + e * acc[ii][1];
        o.z += yd.z + e * acc[ii][2];
        o.w += yd.w + e * acc[ii][3];
        *po = o;
    }
}

// ============================================================================
extern "C" void kernel_launch(void* const* d_in, const int* in_sizes, int n_in,
                              void* d_out, int out_size)
{
    (void)in_sizes; (void)n_in; (void)out_size;
    const float* X  = (const float*)d_in[0];
    const float* A  = (const float*)d_in[1];
    const float* B  = (const float*)d_in[2];
    const float* C  = (const float*)d_in[3];
    const float* r  = (const float*)d_in[4];
    const float* k  = (const float*)d_in[5];
    const float* v  = (const float*)d_in[6];
    const float* w  = (const float*)d_in[7];
    const float* bo = (const float*)d_in[8];
    float* out = (float*)d_out;

    const int FUSED_SMEM = (2 * 64 * 65 + 64 * 64 + 3 * 64) * 4;  // 50432 B
    cudaFuncSetAttribute(fused_kernel,
                         cudaFuncAttributeMaxDynamicSharedMemorySize, FUSED_SMEM);

    fused_kernel<<<1056, 256, FUSED_SMEM>>>(X, A, B, C, r, k, v, w, bo, out);
    scan_kernel<<<128, 1024>>>();
    ssd_off_kernel<<<1024, 256>>>(C, out);
}

// round 7
// speedup vs baseline: 2.7937x; 1.1199x over previous
#include <cuda_runtime.h>
#include <cstdint>
#include <cstddef>

typedef unsigned long long ull;

// Problem constants
// X:(2,2048,16,64) A:(2,2048,16) B,C:(2,2048,16,64)
// r,k,v,w,bonus:(32,2048,64)  out:(2,2048,1024) f32

// ---------------- device scratch (static globals; no allocation) ------------
__device__ float g_states[2*32*16*64*64];   // per-chunk states (b,c,h,p,n)
__device__ float g_R[2*32*16*64*64];        // prefix state entering chunk c
__device__ float g_eA[1024*64];             // exp(cumA[l]) per (b,c,h)
__device__ float g_expsA[32*32];            // exp(chunk-sum A) per (b,h,c)
__device__ float g_yd[2*2048*1024];         // SSD Y_diag scratch

// ---------------- cp.async + f32x2 helpers -----------------------------------
__device__ __forceinline__ void cp_async16(float* dst, const float* src) {
    unsigned s = (unsigned)__cvta_generic_to_shared(dst);
    asm volatile("cp.async.cg.shared.global [%0], [%1], 16;\n" :: "r"(s), "l"(src));
}
__device__ __forceinline__ void cp_commit() { asm volatile("cp.async.commit_group;\n"); }
__device__ __forceinline__ void cp_wait1()  { asm volatile("cp.async.wait_group 1;\n" ::: "memory"); }
__device__ __forceinline__ void cp_wait0()  { asm volatile("cp.async.wait_group 0;\n" ::: "memory"); }

__device__ __forceinline__ ull f2fma(ull a, ull b, ull c) {
    ull d; asm("fma.rn.f32x2 %0, %1, %2, %3;" : "=l"(d) : "l"(a), "l"(b), "l"(c)); return d;
}
__device__ __forceinline__ ull f2mul(ull a, ull b) {
    ull d; asm("mul.rn.f32x2 %0, %1, %2;" : "=l"(d) : "l"(a), "l"(b)); return d;
}
__device__ __forceinline__ ull f2add(ull a, ull b) {
    ull d; asm("add.rn.f32x2 %0, %1, %2;" : "=l"(d) : "l"(a), "l"(b)); return d;
}
__device__ __forceinline__ ull pk2(float lo, float hi) {
    ull r; asm("mov.b64 %0, {%1, %2};" : "=l"(r) : "f"(lo), "f"(hi)); return r;
}
__device__ __forceinline__ float2 upk2(ull p) {
    float2 f; asm("mov.b64 {%0, %1}, %2;" : "=f"(f.x), "=f"(f.y) : "l"(p)); return f;
}

// Chunk swizzle for 64-float rows read as (h2, u) 16B chunks:
// logical chunk c (0..15) -> physical chunk ((c&7)<<1)|(c>>3).
__device__ __forceinline__ int swz_chunk(int c) { return ((c & 7) << 1) | (c >> 3); }
__device__ __forceinline__ int swz_pos(int j)   { return (swz_chunk(j >> 2) << 2) | (j & 3); }

#define BAR_ALL()  asm volatile("bar.sync 1, 256;" ::: "memory")
#define BAR_PROD() asm volatile("bar.sync 2, 128;" ::: "memory")
#define BAR_HELP() asm volatile("bar.sync 3, 128;" ::: "memory")

// SMEM layout for WKV blocks (floats):
//   s_in : [4][5][16][64]  @ 0      (20480)  input ring, k swizzled
//   s_dl : [2][16][64]     @ 20480  (2048)   delta, window-parity buffered
//   s_dk : [16]            @ 22528
// total 22544 floats = 90176 bytes
#define WKV_SMEM_FLOATS 22544

// ============================================================================
// WKV: one CTA per batch-head. Warps 0-3 = recurrence producers (128 thr,
// thread=(row i, half h2)); warps 4-7 = helpers (dk, y, cp.async refill).
// Deferred-decay 2-step fused recurrence:
//  pair (t,t+1): accA=S~k_t, accB=S~k_{t+1} (old S~)
//   d_t = v_t - W accA ; W*=w_t ; c_t = b_t k_ti / W ; store d_t ; bar
//   u = d_t . k_{t+1} ; d_{t+1} = v_{t+1} - W (accB + c_t u) ; W*=w_{t+1}
//   c_{t+1} = b k / W ; store d_{t+1} ; S~ += c_t d_t ; bar
//   S~ += c_{t+1} d_{t+1}
// Window epilogue: S~ *= W, W=1.
// ============================================================================
__device__ __forceinline__ void wkv_producer(int tid, float* sm)
{
    float* s_in = sm;
    const int i  = tid >> 1;
    const int h2 = tid & 1;
    const int pos_i = swz_pos(i);

    ull S2[16];
#pragma unroll
    for (int u = 0; u < 16; ++u) S2[u] = 0ull;
    float W = 1.f;

#pragma unroll 1
    for (int win = 0; win < 128; ++win) {
        const float* pr = s_in + (win & 3) * 5120;
        float* dl = sm + 20480 + (win & 1) * 1024;

#pragma unroll 1
        for (int s = 0; s < 8; ++s) {
            const int st0 = 2 * s, st1 = st0 + 1;
            const float* k0s = pr + 1024 + st0 * 64;
            const float* k1s = pr + 1024 + st1 * 64;

            // ---- phase A: both dots on old S~ ----
            ull ka[16], kb[16];
#pragma unroll
            for (int u = 0; u < 8; ++u) {
                float4 qa = *(const float4*)(k0s + (2 * u + h2) * 4);
                float4 qb = *(const float4*)(k1s + (2 * u + h2) * 4);
                ka[2*u] = *(ull*)&qa.x; ka[2*u+1] = *(ull*)&qa.z;
                kb[2*u] = *(ull*)&qb.x; kb[2*u+1] = *(ull*)&qb.z;
            }
            ull a0 = f2mul(S2[0], ka[0]);
            ull a1 = f2mul(S2[1], ka[1]);
            ull a2 = f2mul(S2[2], ka[2]);
            ull a3 = f2mul(S2[3], ka[3]);
            ull e0 = f2mul(S2[0], kb[0]);
            ull e1 = f2mul(S2[1], kb[1]);
            ull e2 = f2mul(S2[2], kb[2]);
            ull e3 = f2mul(S2[3], kb[3]);
#pragma unroll
            for (int u = 1; u < 4; ++u) {
                a0 = f2fma(S2[4*u+0], ka[4*u+0], a0);
                a1 = f2fma(S2[4*u+1], ka[4*u+1], a1);
                a2 = f2fma(S2[4*u+2], ka[4*u+2], a2);
                a3 = f2fma(S2[4*u+3], ka[4*u+3], a3);
                e0 = f2fma(S2[4*u+0], kb[4*u+0], e0);
                e1 = f2fma(S2[4*u+1], kb[4*u+1], e1);
                e2 = f2fma(S2[4*u+2], kb[4*u+2], e2);
                e3 = f2fma(S2[4*u+3], kb[4*u+3], e3);
            }
            a0 = f2add(a0, a1); a2 = f2add(a2, a3); a0 = f2add(a0, a2);
            e0 = f2add(e0, e1); e2 = f2add(e2, e3); e0 = f2add(e0, e2);
            float2 af = upk2(a0), ef = upk2(e0);
            float accA = af.x + af.y;
            float accB = ef.x + ef.y;
            accA += __shfl_xor_sync(0xffffffffu, accA, 1);
            accB += __shfl_xor_sync(0xffffffffu, accB, 1);

            // row scalars for both steps
            const float v0 = pr[2048 + st0*64 + i];
            const float w0 = pr[3072 + st0*64 + i];
            const float q0 = pr[4096 + st0*64 + i];
            const float k0i = k0s[pos_i];
            const float v1 = pr[2048 + st1*64 + i];
            const float w1 = pr[3072 + st1*64 + i];
            const float q1 = pr[4096 + st1*64 + i];
            const float k1i = k1s[pos_i];

            const float d0 = v0 - W * accA;
            dl[st0*64 + pos_i] = d0;          // both halves store same value
            W *= w0;
            const float c0 = __fdividef(q0 * k0i, W);
            const ull c02 = pk2(c0, c0);
            BAR_PROD();

            // ---- phase B: load d_t, update S~ with c0, u-dot, emit d_{t+1} ----
            ull u0 = 0ull, u1 = 0ull, u2 = 0ull, u3 = 0ull;
            {
                float4 dq0 = *(const float4*)(dl + st0*64 + (0 + h2)*4);
                float4 dq1 = *(const float4*)(dl + st0*64 + (2 + h2)*4);
                float4 dq2 = *(const float4*)(dl + st0*64 + (4 + h2)*4);
                float4 dq3 = *(const float4*)(dl + st0*64 + (6 + h2)*4);
                float4 dq4 = *(const float4*)(dl + st0*64 + (8 + h2)*4);
                float4 dq5 = *(const float4*)(dl + st0*64 + (10 + h2)*4);
                float4 dq6 = *(const float4*)(dl + st0*64 + (12 + h2)*4);
                float4 dq7 = *(const float4*)(dl + st0*64 + (14 + h2)*4);
                ull t0, t1;
#define UPD(Q, base_u) \
                t0 = *(ull*)&Q.x; t1 = *(ull*)&Q.z; \
                u0 = f2fma(t0, kb[2*(base_u)],   u0); \
                u1 = f2fma(t1, kb[2*(base_u)+1], u1); \
                S2[2*(base_u)]   = f2fma(c02, t0, S2[2*(base_u)]); \
                S2[2*(base_u)+1] = f2fma(c02, t1, S2[2*(base_u)+1]);
                UPD(dq0, 0) UPD(dq1, 1) UPD(dq2, 2) UPD(dq3, 3)
#undef UPD
#define UPD2(Q, base_u) \
                t0 = *(ull*)&Q.x; t1 = *(ull*)&Q.z; \
                u2 = f2fma(t0, kb[2*(base_u)],   u2); \
                u3 = f2fma(t1, kb[2*(base_u)+1], u3); \
                S2[2*(base_u)]   = f2fma(c02, t0, S2[2*(base_u)]); \
                S2[2*(base_u)+1] = f2fma(c02, t1, S2[2*(base_u)+1]);
                UPD2(dq4, 4) UPD2(dq5, 5) UPD2(dq6, 6) UPD2(dq7, 7)
#undef UPD2
            }
            u0 = f2add(u0, u1); u2 = f2add(u2, u3); u0 = f2add(u0, u2);
            float2 uf = upk2(u0);
            float uu = uf.x + uf.y;
            uu += __shfl_xor_sync(0xffffffffu, uu, 1);

            const float d1 = v1 - W * fmaf(c0, uu, accB);
            dl[st1*64 + pos_i] = d1;
            W *= w1;
            const float c1 = __fdividef(q1 * k1i, W);
            const ull c12 = pk2(c1, c1);
            BAR_PROD();

            // ---- phase C: update S~ with c1 * d_{t+1} ----
#pragma unroll
            for (int u = 0; u < 8; ++u) {
                float4 dq = *(const float4*)(dl + st1*64 + (2*u + h2)*4);
                S2[2*u]   = f2fma(c12, *(ull*)&dq.x, S2[2*u]);
                S2[2*u+1] = f2fma(c12, *(ull*)&dq.z, S2[2*u+1]);
            }
        }

        // window epilogue: rescale S~ <- diag(W) S~
        {
            const ull w2 = pk2(W, W);
#pragma unroll
            for (int u = 0; u < 16; ++u) S2[u] = f2mul(S2[u], w2);
            W = 1.f;
        }
        BAR_ALL();
    }
}

// Helper warps: dk + y for window wn (reads s_dl[wn&1], s_in[wn&3]).
__device__ __forceinline__ void wkv_emit_window(
    int wn, int tid, float* sm, float* __restrict__ out, int b, int h)
{
    float* s_in = sm;
    float* s_dk = sm + 22528;
    const float* pr = s_in + (wn & 3) * 5120;
    const float* dl = sm + 20480 + (wn & 1) * 1024;
    const int lane = tid & 31, wid = tid >> 5;   // wid 0..3

    // dk[st] = delta . k
#pragma unroll
    for (int rep = 0; rep < 4; ++rep) {
        const int st = rep * 4 + wid;
        const int pp = swz_chunk(lane >> 1) * 4 + (lane & 1) * 2;
        float2 kv  = *(const float2*)(pr + 1024 + st * 64 + pp);
        float2 dl2 = *(const float2*)(dl + st * 64 + pp);
        float pd = fmaf(dl2.x, kv.x, dl2.y * kv.y);
#pragma unroll
        for (int off = 16; off > 0; off >>= 1)
            pd += __shfl_xor_sync(0xffffffffu, pd, off);
        if (lane == 0) s_dk[st] = pd;
    }
    BAR_HELP();

    // y: Sk = v - delta ; y = r*(w*Sk + b*k*dk)
#pragma unroll
    for (int rep = 0; rep < 4; ++rep) {
        const int idx = rep * 128 + tid;        // 0..511 (st, colpair)
        const int st = idx >> 5, cp2 = idx & 31;
        const int col = cp2 * 2;
        const int pp = swz_chunk(cp2 >> 1) * 4 + (cp2 & 1) * 2;
        float2 dv = *(const float2*)(dl + st * 64 + pp);
        float2 k_ = *(const float2*)(pr + 1024 + st * 64 + pp);
        float2 r_ = *(const float2*)(pr + st * 64 + col);
        float2 v_ = *(const float2*)(pr + 2048 + st * 64 + col);
        float2 w_ = *(const float2*)(pr + 3072 + st * 64 + col);
        float2 b_ = *(const float2*)(pr + 4096 + st * 64 + col);
        const float dk = s_dk[st];
        float2 y;
        y.x = r_.x * fmaf(b_.x * k_.x, dk, w_.x * (v_.x - dv.x));
        y.y = r_.y * fmaf(b_.y * k_.y, dk, w_.y * (v_.y - dv.y));
        *(float2*)(out + (size_t)(b * 2048 + wn * 16 + st) * 1024 + h * 64 + col) = y;
    }
}

__device__ __forceinline__ void wkv_helper(
    int tid, float* sm, const float* const* arrs, size_t base,
    float* __restrict__ out, int b, int h)
{
    float* s_in = sm;
#pragma unroll 1
    for (int win = 0; win < 128; ++win) {
        // refill window win+2 into ring slot (win+2)&3
        if (win + 2 < 128) {
            const int dst = ((win + 2) & 3) * 5120;
#pragma unroll
            for (int a = 0; a < 5; ++a)
#pragma unroll
                for (int rep = 0; rep < 2; ++rep) {
                    int x = rep * 128 + tid;     // 0..255
                    int st = x >> 4, c = x & 15;
                    int dc = (a == 1) ? swz_chunk(c) : c;
                    cp_async16(&s_in[dst + a * 1024 + st * 64 + dc * 4],
                               arrs[a] + base + (size_t)((win + 2) * 16 + st) * 64 + c * 4);
                }
            cp_commit();
        }
        if (win >= 1) wkv_emit_window(win - 1, tid, sm, out, b, h);
        cp_wait1();     // guarantees window win+1's group complete
        BAR_ALL();
    }
    wkv_emit_window(127, tid, sm, out, b, h);
}

__device__ __forceinline__ void wkv_block(
    int bh, int tid, float* sm,
    const float* __restrict__ rr, const float* __restrict__ kk_g,
    const float* __restrict__ vv_g, const float* __restrict__ ww_g,
    const float* __restrict__ bo_g, float* __restrict__ out)
{
    const int b = bh >> 4, h = bh & 15;
    const size_t base = (size_t)bh * 2048 * 64;
    const float* arrs[5] = { rr, kk_g, vv_g, ww_g, bo_g };

    // prologue: all 256 threads prefetch windows 0 and 1
#pragma unroll
    for (int wv = 0; wv < 2; ++wv)
#pragma unroll
        for (int a = 0; a < 5; ++a) {
            int st = tid >> 4, c = tid & 15;   // tid 0..255
            int dc = (a == 1) ? swz_chunk(c) : c;
            cp_async16(&sm[wv * 5120 + a * 1024 + st * 64 + dc * 4],
                       arrs[a] + base + (size_t)(wv * 16 + st) * 64 + c * 4);
        }
    cp_commit();
    cp_wait0();
    BAR_ALL();

    if (tid < 128) wkv_producer(tid, sm);
    else           wkv_helper(tid - 128, sm, arrs, base, out, b, h);
}

// ============================================================================
// SSD per-chunk body (writes Y_diag to g_yd; states to g_states)
// ============================================================================
__device__ __forceinline__ void ssd_chunk_body(
    int blk, int tid, float* sm,
    const float* __restrict__ X, const float* __restrict__ A,
    const float* __restrict__ Bm, const float* __restrict__ Cm)
{
    float* sB   = sm;
    float* sG   = sm + 64 * 65;
    float* sX   = sm + 2 * 64 * 65;
    float* s_cum = sX + 4096;
    float* s_eA  = s_cum + 64;
    float* s_ieA = s_eA + 64;

    const int h  = blk & 15;
    const int cc = (blk >> 4) & 31;
    const int b  = blk >> 9;

    const size_t gbase = ((size_t)(b * 2048 + cc * 64) * 16 + h) * 64;
#pragma unroll
    for (int u = 0; u < 4; ++u) {
        int idx4 = u * 256 + tid;
        int l = idx4 >> 4, n4 = (idx4 & 15) * 4;
        size_t go = gbase + (size_t)l * 1024 + n4;
        float4 bv = *(const float4*)(Bm + go);
        float4 cv = *(const float4*)(Cm + go);
        float4 xv = *(const float4*)(X + go);
        float* pb = sB + l * 65 + n4;
        pb[0] = bv.x; pb[1] = bv.y; pb[2] = bv.z; pb[3] = bv.w;
        float* pc = sG + l * 65 + n4;
        pc[0] = cv.x; pc[1] = cv.y; pc[2] = cv.z; pc[3] = cv.w;
        *(float4*)(sX + l * 64 + n4) = xv;
    }
    if (tid < 64) {
        float x = A[(size_t)(b * 2048 + cc * 64 + tid) * 16 + h];
#pragma unroll
        for (int o = 1; o < 32; o <<= 1) {
            float t = __shfl_up_sync(0xffffffffu, x, o);
            if ((tid & 31) >= o) x += t;
        }
        s_cum[tid] = x;
    }
    __syncthreads();
    if (tid < 64) {
        float x = s_cum[tid] + ((tid >= 32) ? s_cum[31] : 0.f);
        float e = expf(x);
        s_eA[tid]  = e;
        s_ieA[tid] = expf(-x);
        g_eA[(size_t)blk * 64 + tid] = e;
        if (tid == 63) g_expsA[(b * 16 + h) * 32 + cc] = e;
    }
    __syncthreads();

    const int tl = tid >> 4, ts = tid & 15;
    const int r0 = tl * 4, c0 = ts * 4;

    float g[4][4];
#pragma unroll
    for (int ii = 0; ii < 4; ++ii)
#pragma unroll
        for (int jj = 0; jj < 4; ++jj) g[ii][jj] = 0.f;
    for (int n = 0; n < 64; ++n) {
        float cl[4], bsv[4];
#pragma unroll
        for (int ii = 0; ii < 4; ++ii) cl[ii] = sG[(r0 + ii) * 65 + n];
#pragma unroll
        for (int jj = 0; jj < 4; ++jj) bsv[jj] = sB[(c0 + jj) * 65 + n];
#pragma unroll
        for (int ii = 0; ii < 4; ++ii)
#pragma unroll
            for (int jj = 0; jj < 4; ++jj) g[ii][jj] = fmaf(cl[ii], bsv[jj], g[ii][jj]);
    }
    __syncthreads();
#pragma unroll
    for (int ii = 0; ii < 4; ++ii) {
        int l = r0 + ii;
        float el = s_eA[l];
#pragma unroll
        for (int jj = 0; jj < 4; ++jj) {
            int s = c0 + jj;
            sG[l * 65 + s] = (s <= l) ? g[ii][jj] * el * s_ieA[s] : 0.f;
        }
    }
    __syncthreads();

    float y[4][4];
#pragma unroll
    for (int ii = 0; ii < 4; ++ii)
#pragma unroll
        for (int jj = 0; jj < 4; ++jj) y[ii][jj] = 0.f;
    for (int s = 0; s < 64; ++s) {
        float4 xv = *(const float4*)(sX + s * 64 + c0);
        float gl[4];
#pragma unroll
        for (int ii = 0; ii < 4; ++ii) gl[ii] = sG[(r0 + ii) * 65 + s];
#pragma unroll
        for (int ii = 0; ii < 4; ++ii) {
            y[ii][0] = fmaf(gl[ii], xv.x, y[ii][0]);
            y[ii][1] = fmaf(gl[ii], xv.y, y[ii][1]);
            y[ii][2] = fmaf(gl[ii], xv.z, y[ii][2]);
            y[ii][3] = fmaf(gl[ii], xv.w, y[ii][3]);
        }
    }
#pragma unroll
    for (int ii = 0; ii < 4; ++ii) {
        int l = r0 + ii;
        *(float4*)(g_yd + (size_t)(b * 2048 + cc * 64 + l) * 1024 + h * 64 + c0) =
            make_float4(y[ii][0], y[ii][1], y[ii][2], y[ii][3]);
    }

    float stt[4][4];
#pragma unroll
    for (int ii = 0; ii < 4; ++ii)
#pragma unroll
        for (int jj = 0; jj < 4; ++jj) stt[ii][jj] = 0.f;
    const float eA63 = s_eA[63];
    for (int l = 0; l < 64; ++l) {
        float ds = eA63 * s_ieA[l];
        float4 xv = *(const float4*)(sX + l * 64 + r0);
        float xw[4] = { xv.x * ds, xv.y * ds, xv.z * ds, xv.w * ds };
        float bv[4];
#pragma unroll
        for (int jj = 0; jj < 4; ++jj) bv[jj] = sB[l * 65 + c0 + jj];
#pragma unroll
        for (int ii = 0; ii < 4; ++ii)
#pragma unroll
            for (int jj = 0; jj < 4; ++jj) stt[ii][jj] = fmaf(xw[ii], bv[jj], stt[ii][jj]);
    }
#pragma unroll
    for (int ii = 0; ii < 4; ++ii)
        *(float4*)(g_states + (size_t)blk * 4096 + (size_t)(r0 + ii) * 64 + c0) =
            make_float4(stt[ii][0], stt[ii][1], stt[ii][2], stt[ii][3]);
}

// ============================================================================
// Fused: blockIdx 0..31 -> WKV, 32..1055 -> SSD chunk (overlapped)
// ============================================================================
__global__ void __launch_bounds__(256, 1) fused_kernel(
    const float* __restrict__ X, const float* __restrict__ A,
    const float* __restrict__ Bm, const float* __restrict__ Cm,
    const float* __restrict__ rr, const float* __restrict__ kk,
    const float* __restrict__ vv, const float* __restrict__ ww,
    const float* __restrict__ bo, float* __restrict__ out)
{
    extern __shared__ float sm[];
    if (blockIdx.x < 32) {
        wkv_block(blockIdx.x, threadIdx.x, sm, rr, kk, vv, ww, bo, out);
    } else {
        ssd_chunk_body(blockIdx.x - 32, threadIdx.x, sm, X, A, Bm, Cm);
    }
}

// ============================================================================
// K2: inter-chunk decay scan
// ============================================================================
__global__ void __launch_bounds__(1024) scan_kernel()
{
    const int bid = blockIdx.x;
    const int bh = bid >> 2, q = bid & 3;
    const int b = bh >> 4, h = bh & 15;
    const int e = q * 1024 + threadIdx.x;
    float R = 0.f;
    const float* es = g_expsA + bh * 32;
#pragma unroll 1
    for (int c = 0; c < 32; ++c) {
        size_t idx = (size_t)(b * 512 + c * 16 + h) * 4096 + e;
        g_R[idx] = R;
        R = fmaf(R, es[c], g_states[idx]);
    }
}

// ============================================================================
// K3: out += g_yd + eA[l] * (C . R^T)
// ============================================================================
__global__ void __launch_bounds__(256) ssd_off_kernel(
    const float* __restrict__ Cm, float* __restrict__ out)
{
    __shared__ float sC[64 * 65];
    __shared__ float sR[64 * 65];
    __shared__ float s_e[64];
    const int blk = blockIdx.x;
    const int h  = blk & 15;
    const int cc = (blk >> 4) & 31;
    const int b  = blk >> 9;
    const int tid = threadIdx.x;

    const size_t gbase = ((size_t)(b * 2048 + cc * 64) * 16 + h) * 64;
#pragma unroll
    for (int u = 0; u < 4; ++u) {
        int idx4 = u * 256 + tid;
        int l = idx4 >> 4, n4 = (idx4 & 15) * 4;
        float4 cv = *(const float4*)(Cm + gbase + (size_t)l * 1024 + n4);
        float4 rv = *(const float4*)(g_R + (size_t)blk * 4096 + (size_t)idx4 * 4);
        float* pc = sC + l * 65 + n4;
        pc[0] = cv.x; pc[1] = cv.y; pc[2] = cv.z; pc[3] = cv.w;
        float* pr = sR + l * 65 + n4;
        pr[0] = rv.x; pr[1] = rv.y; pr[2] = rv.z; pr[3] = rv.w;
    }
    if (tid < 64) s_e[tid] = g_eA[(size_t)blk * 64 + tid];
    __syncthreads();

    const int tl = tid >> 4, ts = tid & 15;
    const int l0 = tl * 4, p0 = ts * 4;

    float acc[4][4];
#pragma unroll
    for (int ii = 0; ii < 4; ++ii)
#pragma unroll
        for (int jj = 0; jj < 4; ++jj) acc[ii][jj] = 0.f;

    for (int n = 0; n < 64; ++n) {
        float cl[4], rv[4];
#pragma unroll
        for (int ii = 0; ii < 4; ++ii) cl[ii] = sC[(l0 + ii) * 65 + n];
#pragma unroll
        for (int jj = 0; jj < 4; ++jj) rv[jj] = sR[(p0 + jj) * 65 + n];
#pragma unroll
        for (int ii = 0; ii < 4; ++ii)
#pragma unroll
            for (int jj = 0; jj < 4; ++jj) acc[ii][jj] = fmaf(cl[ii], rv[jj], acc[ii][jj]);
    }
#pragma unroll
    for (int ii = 0; ii < 4; ++ii) {
        int l = l0 + ii;
        float e = s_e[l];
        size_t ofs = (size_t)(b * 2048 + cc * 64 + l) * 1024 + h * 64 + p0;
        float4* po = (float4*)(out + ofs);
        float4 o  = *po;
        float4 yd = *(const float4*)(g_yd + ofs);
        o.x += yd.x + e * acc[ii][0];
        o.y += yd.y + e * acc[ii][1];
        o.z += yd.z + e * acc[ii][2];
        o.w += yd.w + e * acc[ii][3];
        *po = o;
    }
}

// ============================================================================
extern "C" void kernel_launch(void* const* d_in, const int* in_sizes, int n_in,
                              void* d_out, int out_size)
{
    (void)in_sizes; (void)n_in; (void)out_size;
    const float* X  = (const float*)d_in[0];
    const float* A  = (const float*)d_in[1];
    const float* B  = (const float*)d_in[2];
    const float* C  = (const float*)d_in[3];
    const float* r  = (const float*)d_in[4];
    const float* k  = (const float*)d_in[5];
    const float* v  = (const float*)d_in[6];
    const float* w  = (const float*)d_in[7];
    const float* bo = (const float*)d_in[8];
    float* out = (float*)d_out;

    const int SSD_SMEM = (2 * 64 * 65 + 64 * 64 + 3 * 64) * 4;   // 50432 B
    const int WKV_SMEM = WKV_SMEM_FLOATS * 4;                    // 90176 B
    const int FUSED_SMEM = (WKV_SMEM > SSD_SMEM) ? WKV_SMEM : SSD_SMEM;
    cudaFuncSetAttribute(fused_kernel,
                         cudaFuncAttributeMaxDynamicSharedMemorySize, FUSED_SMEM);

    fused_kernel<<<1056, 256, FUSED_SMEM>>>(X, A, B, C, r, k, v, w, bo, out);
    scan_kernel<<<128, 1024>>>();
    ssd_off_kernel<<<1024, 256>>>(C, out);
}